// round 14
// baseline (speedup 1.0000x reference)
#include <cuda_runtime.h>
#include <cuda_bf16.h>
#include <cstdint>
#include <math.h>

#define BB    8
#define CIN   256
#define CMID  128
#define PP    3600            // 60*60 positions per batch image
#define NPOS  (BB * PP)       // 28800
#define JT    57              // ceil(3600/64) j-tiles (loss)
#define IT    29              // ceil(3600/128) i-tiles

// -------- device scratch (module-scope; no runtime alloc) --------
__device__ __nv_bfloat16 g_hidbf[(size_t)2 * BB * PP * CMID];  // conv output (bf16)
__device__ unsigned char g_featq[(size_t)2 * BB * PP * CMID];  // normalized features (e4m3)
__device__ float g_sum[256], g_sumsq[256];
__device__ float g_scale[256], g_shift[256];
__device__ float g_loss;

__device__ __forceinline__ uint32_t s2u(const void* p) {
    return (uint32_t)__cvta_generic_to_shared(p);
}
__device__ __forceinline__ float ex2(float x) {      // EX2 (MUFU), base-2 exp
    float y;
    asm("ex2.approx.f32 %0, %1;" : "=f"(y) : "f"(x));
    return y;
}
// pack (lo, hi) floats -> e4m3x2 (lo in low byte)
__device__ __forceinline__ uint16_t f2_e4m3(float lo, float hi) {
    uint16_t v;
    asm("cvt.rn.satfinite.e4m3x2.f32 %0, %1, %2;" : "=h"(v) : "f"(hi), "f"(lo));
    return v;
}
#define LDSM4(r0,r1,r2,r3,addr) \
    asm volatile("ldmatrix.sync.aligned.m8n8.x4.shared.b16 {%0,%1,%2,%3}, [%4];" \
        : "=r"(r0),"=r"(r1),"=r"(r2),"=r"(r3) : "r"(addr))
#define LDSM4T(r0,r1,r2,r3,addr) \
    asm volatile("ldmatrix.sync.aligned.m8n8.x4.trans.shared.b16 {%0,%1,%2,%3}, [%4];" \
        : "=r"(r0),"=r"(r1),"=r"(r2),"=r"(r3) : "r"(addr))
#define MMA16816(d0,d1,d2,d3,a0,a1,a2,a3,b0,b1) \
    asm volatile("mma.sync.aligned.m16n8k16.row.col.f32.bf16.bf16.f32 " \
        "{%0,%1,%2,%3}, {%4,%5,%6,%7}, {%8,%9}, {%0,%1,%2,%3};" \
        : "+f"(d0),"+f"(d1),"+f"(d2),"+f"(d3) \
        : "r"(a0),"r"(a1),"r"(a2),"r"(a3),"r"(b0),"r"(b1))
#define MMAFP8(d0,d1,d2,d3,a0,a1,a2,a3,b0,b1) \
    asm volatile("mma.sync.aligned.m16n8k32.row.col.f32.e4m3.e4m3.f32 " \
        "{%0,%1,%2,%3}, {%4,%5,%6,%7}, {%8,%9}, {%0,%1,%2,%3};" \
        : "+f"(d0),"+f"(d1),"+f"(d2),"+f"(d3) \
        : "r"(a0),"r"(a1),"r"(a2),"r"(a3),"r"(b0),"r"(b1))

// ---------------------------------------------------------------------
__global__ void zero_kernel() {
    int t = threadIdx.x;
    if (t < 256) { g_sum[t] = 0.f; g_sumsq[t] = 0.f; }
    if (t == 0) g_loss = 0.f;
}

// ---------------------------------------------------------------------
// Kernel A (tensor, double-buffered): hid[p,co] = cw[co,:].relu(x[:,p]) + cb
__global__ void __launch_bounds__(256) conv_kernel(
    const float* __restrict__ x0, const float* __restrict__ x1,
    const float* __restrict__ cw, const float* __restrict__ cb)
{
    const int s = blockIdx.z, b = blockIdx.y;
    const int i0 = blockIdx.x * 128;
    const float* x = (s == 0 ? x0 : x1) + (size_t)b * CIN * PP;

    __shared__ __nv_bfloat16 Xs[2][32][136];
    __shared__ __nv_bfloat16 Ws[2][128][40];
    __shared__ float ssum[128], ssq[128];

    const int t = threadIdx.x;
    const int wid = t >> 5, lane = t & 31;
    const int wm = wid & 3, wn = wid >> 2;
    const int mb = wm * 32, nb = wn * 64;
    const int g = lane >> 2, tg = lane & 3;
    const int lr = lane & 7, lq = lane >> 3;

    if (t < 128) { ssum[t] = 0.f; ssq[t] = 0.f; }

    const int xci = t >> 5, xpg = t & 31;
    const int wco = t >> 3, wf  = (t & 7) * 4;

    float4 xv[4], wv[4];
#pragma unroll
    for (int u = 0; u < 4; u++) {
        int p = i0 + xpg * 4;
        xv[u] = make_float4(0.f, 0.f, 0.f, 0.f);
        if (p < PP) xv[u] = *(const float4*)(x + (size_t)(xci + u * 8) * PP + p);
        wv[u] = *(const float4*)(cw + (size_t)(wco + u * 32) * CIN + wf);
    }
#pragma unroll
    for (int u = 0; u < 4; u++) {
        __nv_bfloat162 h0 = __floats2bfloat162_rn(fmaxf(xv[u].x, 0.f), fmaxf(xv[u].y, 0.f));
        __nv_bfloat162 h1 = __floats2bfloat162_rn(fmaxf(xv[u].z, 0.f), fmaxf(xv[u].w, 0.f));
        *(uint2*)&Xs[0][xci + u * 8][xpg * 4] =
            make_uint2(*(uint32_t*)&h0, *(uint32_t*)&h1);
        __nv_bfloat162 g0 = __floats2bfloat162_rn(wv[u].x, wv[u].y);
        __nv_bfloat162 g1 = __floats2bfloat162_rn(wv[u].z, wv[u].w);
        *(uint2*)&Ws[0][wco + u * 32][wf] =
            make_uint2(*(uint32_t*)&g0, *(uint32_t*)&g1);
    }
    __syncthreads();

    float dacc[2][8][4];
#pragma unroll
    for (int mt = 0; mt < 2; mt++)
#pragma unroll
        for (int nt = 0; nt < 8; nt++)
#pragma unroll
            for (int c = 0; c < 4; c++) dacc[mt][nt][c] = 0.f;

    for (int chunk = 0; chunk < 8; chunk++) {
        const int cur = chunk & 1;
        if (chunk < 7) {
            int kc = (chunk + 1) * 32;
#pragma unroll
            for (int u = 0; u < 4; u++) {
                int p = i0 + xpg * 4;
                xv[u] = make_float4(0.f, 0.f, 0.f, 0.f);
                if (p < PP)
                    xv[u] = *(const float4*)(x + (size_t)(kc + xci + u * 8) * PP + p);
                wv[u] = *(const float4*)(cw + (size_t)(wco + u * 32) * CIN + kc + wf);
            }
        }
#pragma unroll
        for (int ks = 0; ks < 2; ks++) {
            uint32_t a[2][4];
#pragma unroll
            for (int mt = 0; mt < 2; mt++) {
                uint32_t addr = s2u(&Xs[cur][ks * 16 + (lq >> 1) * 8 + lr]
                                          [mb + mt * 16 + (lq & 1) * 8]);
                LDSM4T(a[mt][0], a[mt][1], a[mt][2], a[mt][3], addr);
            }
#pragma unroll
            for (int q = 0; q < 4; q++) {
                uint32_t b0, b1, b2, b3;
                uint32_t addr = s2u(&Ws[cur][nb + (q * 2 + (lq >> 1)) * 8 + lr]
                                          [ks * 16 + (lq & 1) * 8]);
                LDSM4(b0, b1, b2, b3, addr);
#pragma unroll
                for (int mt = 0; mt < 2; mt++) {
                    MMA16816(dacc[mt][q*2][0], dacc[mt][q*2][1],
                             dacc[mt][q*2][2], dacc[mt][q*2][3],
                             a[mt][0], a[mt][1], a[mt][2], a[mt][3], b0, b1);
                    MMA16816(dacc[mt][q*2+1][0], dacc[mt][q*2+1][1],
                             dacc[mt][q*2+1][2], dacc[mt][q*2+1][3],
                             a[mt][0], a[mt][1], a[mt][2], a[mt][3], b2, b3);
                }
            }
        }
        if (chunk < 7) {
            const int nxt = cur ^ 1;
#pragma unroll
            for (int u = 0; u < 4; u++) {
                __nv_bfloat162 h0 = __floats2bfloat162_rn(fmaxf(xv[u].x, 0.f), fmaxf(xv[u].y, 0.f));
                __nv_bfloat162 h1 = __floats2bfloat162_rn(fmaxf(xv[u].z, 0.f), fmaxf(xv[u].w, 0.f));
                *(uint2*)&Xs[nxt][xci + u * 8][xpg * 4] =
                    make_uint2(*(uint32_t*)&h0, *(uint32_t*)&h1);
                __nv_bfloat162 g0 = __floats2bfloat162_rn(wv[u].x, wv[u].y);
                __nv_bfloat162 g1 = __floats2bfloat162_rn(wv[u].z, wv[u].w);
                *(uint2*)&Ws[nxt][wco + u * 32][wf] =
                    make_uint2(*(uint32_t*)&g0, *(uint32_t*)&g1);
            }
        }
        __syncthreads();
    }

    __nv_bfloat16* hid = g_hidbf + (size_t)s * (BB * (size_t)PP * CMID)
                                 + (size_t)b * PP * CMID;
    float lsum[16], lsq[16];
#pragma unroll
    for (int i = 0; i < 16; i++) { lsum[i] = 0.f; lsq[i] = 0.f; }

#pragma unroll
    for (int mt = 0; mt < 2; mt++)
#pragma unroll
        for (int hi = 0; hi < 2; hi++) {
            int lrow = mb + mt * 16 + hi * 8 + g;
            int row = i0 + lrow;
            if (row < PP) {
#pragma unroll
                for (int nt = 0; nt < 8; nt++) {
                    int col = nb + nt * 8 + tg * 2;
                    float y0 = dacc[mt][nt][hi * 2]     + cb[col];
                    float y1 = dacc[mt][nt][hi * 2 + 1] + cb[col + 1];
                    lsum[nt*2]   += y0;  lsq[nt*2]   += y0 * y0;
                    lsum[nt*2+1] += y1;  lsq[nt*2+1] += y1 * y1;
                    __nv_bfloat162 h = __floats2bfloat162_rn(y0, y1);
                    *(uint32_t*)(hid + (size_t)row * CMID + col) = *(uint32_t*)&h;
                }
            }
        }
#pragma unroll
    for (int i = 0; i < 16; i++) {
        lsum[i] += __shfl_xor_sync(0xffffffffu, lsum[i], 4);
        lsum[i] += __shfl_xor_sync(0xffffffffu, lsum[i], 8);
        lsum[i] += __shfl_xor_sync(0xffffffffu, lsum[i], 16);
        lsq[i]  += __shfl_xor_sync(0xffffffffu, lsq[i],  4);
        lsq[i]  += __shfl_xor_sync(0xffffffffu, lsq[i],  8);
        lsq[i]  += __shfl_xor_sync(0xffffffffu, lsq[i],  16);
    }
    if (g == 0) {
#pragma unroll
        for (int nt = 0; nt < 8; nt++) {
            int col = nb + nt * 8 + tg * 2;
            atomicAdd(&ssum[col],     lsum[nt*2]);
            atomicAdd(&ssum[col + 1], lsum[nt*2+1]);
            atomicAdd(&ssq[col],      lsq[nt*2]);
            atomicAdd(&ssq[col + 1],  lsq[nt*2+1]);
        }
    }
    __syncthreads();
    if (t < 128) {
        atomicAdd(&g_sum  [s * 128 + t], ssum[t]);
        atomicAdd(&g_sumsq[s * 128 + t], ssq[t]);
    }
}

// ---------------------------------------------------------------------
__global__ void stats_kernel(const float* __restrict__ gamma,
                             const float* __restrict__ beta)
{
    int s = blockIdx.x, c = threadIdx.x;
    if (c < 128) {
        float n = (float)NPOS;
        float mean = g_sum[s * 128 + c] / n;
        float var  = g_sumsq[s * 128 + c] / n - mean * mean;
        float rs   = rsqrtf(var + 1e-5f);
        float scl  = gamma[c] * rs;
        g_scale[s * 128 + c] = scl;
        g_shift[s * 128 + c] = beta[c] - mean * scl;
    }
}

// ---------------------------------------------------------------------
// Kernel C (tensor): feat = normalize(lin_w . relu(affine(hid)) + lb) -> e4m3
__global__ void __launch_bounds__(256) feat_kernel(
    const float* __restrict__ lw, const float* __restrict__ lb)
{
    extern __shared__ __align__(16) unsigned char smraw[];
    __nv_bfloat16* As = (__nv_bfloat16*)smraw;           // 128 x 136
    __nv_bfloat16* Ws = As + 128 * 136;                  // 128 x 136
    float* psum = (float*)(Ws + 128 * 136);              // 128

    const int s = blockIdx.z, b = blockIdx.y;
    const int i0 = blockIdx.x * 128;
    const int t = threadIdx.x;
    const int wid = t >> 5, lane = t & 31;
    const int wm = wid & 3, wn = wid >> 2;
    const int mb = wm * 32, nb = wn * 64;
    const int g = lane >> 2, tg = lane & 3;
    const int lr = lane & 7, lq = lane >> 3;

    const __nv_bfloat16* hid = g_hidbf + (size_t)s * (BB * (size_t)PP * CMID)
                                       + (size_t)b * PP * CMID;
    const float* sc = g_scale + s * 128;
    const float* sh = g_shift + s * 128;

    if (t < 128) psum[t] = 0.f;

#pragma unroll
    for (int u = 0; u < 8; u++) {
        int idx = u * 256 + t;
        int row = idx >> 4, seg = idx & 15;
        int k0 = seg * 8;
        uint2 out[2];
        if (i0 + row < PP) {
            uint4 v = *(const uint4*)(hid + (size_t)(i0 + row) * CMID + k0);
            uint32_t w[4] = {v.x, v.y, v.z, v.w};
#pragma unroll
            for (int j = 0; j < 4; j++) {
                float2 f = __bfloat1622float2(*(__nv_bfloat162*)&w[j]);
                float y0 = fmaxf(fmaf(f.x, sc[k0 + 2*j],     sh[k0 + 2*j]),     0.f);
                float y1 = fmaxf(fmaf(f.y, sc[k0 + 2*j + 1], sh[k0 + 2*j + 1]), 0.f);
                __nv_bfloat162 h = __floats2bfloat162_rn(y0, y1);
                ((uint32_t*)out)[j] = *(uint32_t*)&h;
            }
        } else {
            out[0] = make_uint2(0u, 0u); out[1] = make_uint2(0u, 0u);
        }
        *(uint4*)&As[row * 136 + k0] = *(uint4*)out;
    }
#pragma unroll
    for (int u = 0; u < 16; u++) {
        int idx = u * 256 + t;
        int co = idx >> 5, f = (idx & 31) * 4;
        float4 v = *(const float4*)(lw + (size_t)co * CMID + f);
        __nv_bfloat162 h0 = __floats2bfloat162_rn(v.x, v.y);
        __nv_bfloat162 h1 = __floats2bfloat162_rn(v.z, v.w);
        uint2 pk = make_uint2(*(uint32_t*)&h0, *(uint32_t*)&h1);
        *(uint2*)&Ws[co * 136 + f] = pk;
    }
    __syncthreads();

    float dacc[2][8][4];
#pragma unroll
    for (int mt = 0; mt < 2; mt++)
#pragma unroll
        for (int nt = 0; nt < 8; nt++)
#pragma unroll
            for (int c = 0; c < 4; c++) dacc[mt][nt][c] = 0.f;

#pragma unroll
    for (int ks = 0; ks < 8; ks++) {
        uint32_t a[2][4];
#pragma unroll
        for (int mt = 0; mt < 2; mt++) {
            uint32_t addr = s2u(&As[(mb + mt * 16 + (lq & 1) * 8 + lr) * 136
                                    + ks * 16 + (lq >> 1) * 8]);
            LDSM4(a[mt][0], a[mt][1], a[mt][2], a[mt][3], addr);
        }
#pragma unroll
        for (int q = 0; q < 4; q++) {
            uint32_t b0, b1, b2, b3;
            uint32_t addr = s2u(&Ws[(nb + (q * 2 + (lq >> 1)) * 8 + lr) * 136
                                    + ks * 16 + (lq & 1) * 8]);
            LDSM4(b0, b1, b2, b3, addr);
#pragma unroll
            for (int mt = 0; mt < 2; mt++) {
                MMA16816(dacc[mt][q*2][0], dacc[mt][q*2][1],
                         dacc[mt][q*2][2], dacc[mt][q*2][3],
                         a[mt][0], a[mt][1], a[mt][2], a[mt][3], b0, b1);
                MMA16816(dacc[mt][q*2+1][0], dacc[mt][q*2+1][1],
                         dacc[mt][q*2+1][2], dacc[mt][q*2+1][3],
                         a[mt][0], a[mt][1], a[mt][2], a[mt][3], b2, b3);
            }
        }
    }

    float rsq[4] = {0.f, 0.f, 0.f, 0.f};
#pragma unroll
    for (int mt = 0; mt < 2; mt++)
#pragma unroll
        for (int hi = 0; hi < 2; hi++) {
#pragma unroll
            for (int nt = 0; nt < 8; nt++) {
                int col = nb + nt * 8 + tg * 2;
                float y0 = dacc[mt][nt][hi*2]   + lb[col];
                float y1 = dacc[mt][nt][hi*2+1] + lb[col + 1];
                dacc[mt][nt][hi*2]   = y0;
                dacc[mt][nt][hi*2+1] = y1;
                rsq[mt*2+hi] = fmaf(y0, y0, fmaf(y1, y1, rsq[mt*2+hi]));
            }
        }
#pragma unroll
    for (int r = 0; r < 4; r++) {
        rsq[r] += __shfl_xor_sync(0xffffffffu, rsq[r], 1);
        rsq[r] += __shfl_xor_sync(0xffffffffu, rsq[r], 2);
    }
    if (tg == 0) {
#pragma unroll
        for (int r = 0; r < 4; r++) {
            int lrow = mb + (r >> 1) * 16 + (r & 1) * 8 + g;
            atomicAdd(&psum[lrow], rsq[r]);
        }
    }
    __syncthreads();

    unsigned char* ft = g_featq + (size_t)s * (BB * (size_t)PP * CMID)
                                + (size_t)b * PP * CMID;
#pragma unroll
    for (int mt = 0; mt < 2; mt++)
#pragma unroll
        for (int hi = 0; hi < 2; hi++) {
            int lrow = mb + mt * 16 + hi * 8 + g;
            int row = i0 + lrow;
            if (row < PP) {
                float inv = 1.f / fmaxf(sqrtf(psum[lrow]), 1e-12f);
#pragma unroll
                for (int nt = 0; nt < 8; nt++) {
                    int col = nb + nt * 8 + tg * 2;
                    uint16_t v = f2_e4m3(dacc[mt][nt][hi*2] * inv,
                                         dacc[mt][nt][hi*2+1] * inv);
                    *(uint16_t*)(ft + (size_t)row * CMID + col) = v;
                }
            }
        }
}

// ---------------------------------------------------------------------
// Kernel D: e4m3 mma.sync (m16n8k32) logits GEMM + fused exp-sum + diag.
// Same fragment index math as bf16-k16 (b16 unit = 2 fp8). occupancy 2.
__global__ void __launch_bounds__(256, 2) loss_kernel()
{
    extern __shared__ __align__(16) unsigned char smraw[];
    unsigned char* obuf = smraw;                         // 128 x 144 bytes
    unsigned char* tbuf = obuf + 128 * 144;              // 64 x 144 bytes
    float* rowsum = (float*)(tbuf + 64 * 144);           // 128
    float* rowpos = rowsum + 128;                        // 128
    __shared__ float cred[256];

    const int b  = blockIdx.y;
    const int i0 = blockIdx.x * 128;
    const int t  = threadIdx.x;
    const int wid = t >> 5, lane = t & 31;
    const int wm = wid & 3, wn = wid >> 2;
    const int mb = wm * 32, nb = wn * 32;
    const int g = lane >> 2, tg = lane & 3;
    const int lr = lane & 7, lq = lane >> 3;
    const float invT = 1.0f / 0.07f;
    const float C2 = invT * 1.44269504088896f;   // invT * log2(e)

    const unsigned char* fo  = g_featq + (size_t)b * PP * CMID;
    const unsigned char* ftg = g_featq + (size_t)BB * PP * CMID + (size_t)b * PP * CMID;

    if (t < 128) rowsum[t] = 0.f;

    // stage o tile: 128 rows x 8 uint4-segs (128 B/row)
#pragma unroll
    for (int u = 0; u < 4; u++) {
        int idx = u * 256 + t;
        int row = idx >> 3, seg = idx & 7;
        uint4 v = make_uint4(0u, 0u, 0u, 0u);
        int ig = i0 + row;
        if (ig < PP) v = *(const uint4*)(fo + (size_t)ig * CMID + seg * 16);
        *(uint4*)(obuf + row * 144 + seg * 16) = v;
    }
    __syncthreads();

    // A fragments resident: 2 m-tiles x 4 k-steps (k=32 fp8 each) x 4 regs
    uint32_t a[2][4][4];
#pragma unroll
    for (int mt = 0; mt < 2; mt++)
#pragma unroll
        for (int ks = 0; ks < 4; ks++) {
            int mrow = mb + mt * 16 + (lq & 1) * 8 + lr;
            int koff = ks * 32 + (lq >> 1) * 16;         // bytes
            uint32_t addr = s2u(obuf + mrow * 144 + koff);
            LDSM4(a[mt][ks][0], a[mt][ks][1], a[mt][ks][2], a[mt][ks][3], addr);
        }

    float dacc[2][4][4];
#pragma unroll
    for (int mt = 0; mt < 2; mt++)
#pragma unroll
        for (int nt = 0; nt < 4; nt++)
#pragma unroll
            for (int c = 0; c < 4; c++) dacc[mt][nt][c] = 0.f;
    float sacc[4] = {0.f, 0.f, 0.f, 0.f};

    for (int jt = 0; jt < JT; jt++) {
        int j0 = jt * 64;
        __syncthreads();
        // stage t tile: 64 rows x 8 uint4-segs = 512 stores
#pragma unroll
        for (int u = 0; u < 2; u++) {
            int idx = u * 256 + t;
            int row = idx >> 3, seg = idx & 7;
            uint4 v = make_uint4(0u, 0u, 0u, 0u);
            int jg = j0 + row;
            if (jg < PP) v = *(const uint4*)(ftg + (size_t)jg * CMID + seg * 16);
            *(uint4*)(tbuf + row * 144 + seg * 16) = v;
        }
        __syncthreads();

#pragma unroll
        for (int ks = 0; ks < 4; ks++) {
#pragma unroll
            for (int q = 0; q < 2; q++) {
                uint32_t b0, b1, b2, b3;
                int brow = nb + (q * 2 + (lq >> 1)) * 8 + lr;
                int koff = ks * 32 + (lq & 1) * 16;      // bytes
                uint32_t addr = s2u(tbuf + brow * 144 + koff);
                LDSM4(b0, b1, b2, b3, addr);
#pragma unroll
                for (int mt = 0; mt < 2; mt++) {
                    MMAFP8(dacc[mt][q*2][0], dacc[mt][q*2][1],
                           dacc[mt][q*2][2], dacc[mt][q*2][3],
                           a[mt][ks][0], a[mt][ks][1], a[mt][ks][2], a[mt][ks][3],
                           b0, b1);
                    MMAFP8(dacc[mt][q*2+1][0], dacc[mt][q*2+1][1],
                           dacc[mt][q*2+1][2], dacc[mt][q*2+1][3],
                           a[mt][ks][0], a[mt][ks][1], a[mt][ks][2], a[mt][ks][3],
                           b2, b3);
                }
            }
        }

        // epilogue
        int dj = jt - (blockIdx.x << 1);
        if (jt < 56 && (unsigned)dj > 1u) {
#pragma unroll
            for (int mt = 0; mt < 2; mt++)
#pragma unroll
                for (int nt = 0; nt < 4; nt++)
#pragma unroll
                    for (int c = 0; c < 4; c++) {
                        sacc[mt * 2 + (c >> 1)] += ex2(dacc[mt][nt][c] * C2);
                        dacc[mt][nt][c] = 0.f;
                    }
        } else {
#pragma unroll
            for (int mt = 0; mt < 2; mt++)
#pragma unroll
                for (int nt = 0; nt < 4; nt++)
#pragma unroll
                    for (int c = 0; c < 4; c++) {
                        float d = dacc[mt][nt][c];
                        int hi  = c >> 1;
                        int col = j0 + nb + nt * 8 + tg * 2 + (c & 1);
                        int lrow = mb + mt * 16 + hi * 8 + g;
                        if (col < PP) {
                            sacc[mt * 2 + hi] += ex2(d * C2);
                            if (col == i0 + lrow) rowpos[lrow] = d * invT;
                        }
                        dacc[mt][nt][c] = 0.f;
                    }
        }
    }

#pragma unroll
    for (int r = 0; r < 4; r++) {
        sacc[r] += __shfl_xor_sync(0xffffffffu, sacc[r], 1);
        sacc[r] += __shfl_xor_sync(0xffffffffu, sacc[r], 2);
    }
    if (tg == 0) {
#pragma unroll
        for (int r = 0; r < 4; r++) {
            int lrow = mb + (r >> 1) * 16 + (r & 1) * 8 + g;
            atomicAdd(&rowsum[lrow], sacc[r]);
        }
    }
    __syncthreads();

    float contrib = 0.f;
    if (t < 128) {
        int ig = i0 + t;
        if (ig < PP) contrib = logf(rowsum[t]) - rowpos[t];
    }
    cred[t] = contrib;
    __syncthreads();
#pragma unroll
    for (int off = 128; off > 0; off >>= 1) {
        if (t < off) cred[t] += cred[t + off];
        __syncthreads();
    }
    if (t == 0) atomicAdd(&g_loss, cred[0]);
}

// ---------------------------------------------------------------------
__global__ void finalize_kernel(float* __restrict__ out) {
    out[0] = g_loss * (1.0f / (float)NPOS);
}

// ---------------------------------------------------------------------
extern "C" void kernel_launch(void* const* d_in, const int* in_sizes, int n_in,
                              void* d_out, int out_size)
{
    const float* x0    = (const float*)d_in[0];
    const float* x1    = (const float*)d_in[1];
    const float* cw    = (const float*)d_in[2];
    const float* cb    = (const float*)d_in[3];
    const float* gamma = (const float*)d_in[4];
    const float* beta  = (const float*)d_in[5];
    const float* lw    = (const float*)d_in[6];
    const float* lb    = (const float*)d_in[7];
    float* out = (float*)d_out;

    size_t fsm = (size_t)(2 * 128 * 136) * sizeof(__nv_bfloat16)
               + 128 * sizeof(float);   // 70144 B
    cudaFuncSetAttribute((const void*)feat_kernel,
                         cudaFuncAttributeMaxDynamicSharedMemorySize, (int)fsm);
    size_t lsm = (size_t)(128 * 144 + 64 * 144) + 256 * sizeof(float); // 28672 B
    cudaFuncSetAttribute((const void*)loss_kernel,
                         cudaFuncAttributeMaxDynamicSharedMemorySize, (int)lsm);

    zero_kernel<<<1, 256>>>();
    conv_kernel<<<dim3(IT, 8, 2), 256>>>(x0, x1, cw, cb);
    stats_kernel<<<2, 128>>>(gamma, beta);
    feat_kernel<<<dim3(IT, 8, 2), 256, fsm>>>(lw, lb);
    loss_kernel<<<dim3(IT, 8), 256, lsm>>>();
    finalize_kernel<<<1, 1>>>(out);
}

// round 15
// speedup vs baseline: 1.0467x; 1.0467x over previous
#include <cuda_runtime.h>
#include <cuda_bf16.h>
#include <cstdint>
#include <math.h>

#define BB    8
#define CIN   256
#define CMID  128
#define PP    3600            // 60*60 positions per batch image
#define NPOS  (BB * PP)       // 28800
#define JT    57              // ceil(3600/64) j-tiles (loss)
#define IT    29              // ceil(3600/128) i-tiles (loss)
#define FT    57              // ceil(3600/64) tiles (conv/feat)

// -------- device scratch (module-scope; no runtime alloc) --------
__device__ __nv_bfloat16 g_hidbf[(size_t)2 * BB * PP * CMID];  // conv output (bf16)
__device__ __nv_bfloat16 g_featbf[(size_t)2 * BB * PP * CMID]; // normalized features (bf16)
__device__ float g_sum[256], g_sumsq[256];
__device__ float g_scale[256], g_shift[256];
__device__ float g_loss;

__device__ __forceinline__ uint32_t s2u(const void* p) {
    return (uint32_t)__cvta_generic_to_shared(p);
}
__device__ __forceinline__ float ex2(float x) {      // EX2 (MUFU), base-2 exp
    float y;
    asm("ex2.approx.f32 %0, %1;" : "=f"(y) : "f"(x));
    return y;
}
#define LDSM4(r0,r1,r2,r3,addr) \
    asm volatile("ldmatrix.sync.aligned.m8n8.x4.shared.b16 {%0,%1,%2,%3}, [%4];" \
        : "=r"(r0),"=r"(r1),"=r"(r2),"=r"(r3) : "r"(addr))
#define LDSM4T(r0,r1,r2,r3,addr) \
    asm volatile("ldmatrix.sync.aligned.m8n8.x4.trans.shared.b16 {%0,%1,%2,%3}, [%4];" \
        : "=r"(r0),"=r"(r1),"=r"(r2),"=r"(r3) : "r"(addr))
#define MMA16816(d0,d1,d2,d3,a0,a1,a2,a3,b0,b1) \
    asm volatile("mma.sync.aligned.m16n8k16.row.col.f32.bf16.bf16.f32 " \
        "{%0,%1,%2,%3}, {%4,%5,%6,%7}, {%8,%9}, {%0,%1,%2,%3};" \
        : "+f"(d0),"+f"(d1),"+f"(d2),"+f"(d3) \
        : "r"(a0),"r"(a1),"r"(a2),"r"(a3),"r"(b0),"r"(b1))

// ---------------------------------------------------------------------
__global__ void zero_kernel() {
    int t = threadIdx.x;
    if (t < 256) { g_sum[t] = 0.f; g_sumsq[t] = 0.f; }
    if (t == 0) g_loss = 0.f;
}

// ---------------------------------------------------------------------
// Kernel A (tensor, double-buffered, 64-pos tiles): hid = cw . relu(x) + cb
// Warp tile 16p x 64co (8 warps: 4 m-quarters x 2 n-halves). occ 3.
__global__ void __launch_bounds__(256) conv_kernel(
    const float* __restrict__ x0, const float* __restrict__ x1,
    const float* __restrict__ cw, const float* __restrict__ cb)
{
    const int s = blockIdx.z, b = blockIdx.y;
    const int i0 = blockIdx.x * 64;
    const float* x = (s == 0 ? x0 : x1) + (size_t)b * CIN * PP;

    __shared__ __nv_bfloat16 Xs[2][32][72];
    __shared__ __nv_bfloat16 Ws[2][128][40];
    __shared__ float ssum[128], ssq[128];

    const int t = threadIdx.x;
    const int wid = t >> 5, lane = t & 31;
    const int wm = wid & 3, wn = wid >> 2;
    const int mb = wm * 16, nb = wn * 64;
    const int g = lane >> 2, tg = lane & 3;
    const int lr = lane & 7, lq = lane >> 3;

    if (t < 128) { ssum[t] = 0.f; ssq[t] = 0.f; }

    // staging coords: Xs (u<2): ci = xci + u*16, p-seg fixed; Ws (u<4)
    const int xci = t >> 4, xp0 = (t & 15) * 4;
    const int wco = t >> 3, wf  = (t & 7) * 4;

    float4 xv[2], wv[4];
#pragma unroll
    for (int u = 0; u < 2; u++) {
        xv[u] = make_float4(0.f, 0.f, 0.f, 0.f);
        if (i0 + xp0 < PP)
            xv[u] = *(const float4*)(x + (size_t)(xci + u * 16) * PP + i0 + xp0);
    }
#pragma unroll
    for (int u = 0; u < 4; u++)
        wv[u] = *(const float4*)(cw + (size_t)(wco + u * 32) * CIN + wf);

#pragma unroll
    for (int u = 0; u < 2; u++) {
        __nv_bfloat162 h0 = __floats2bfloat162_rn(fmaxf(xv[u].x, 0.f), fmaxf(xv[u].y, 0.f));
        __nv_bfloat162 h1 = __floats2bfloat162_rn(fmaxf(xv[u].z, 0.f), fmaxf(xv[u].w, 0.f));
        *(uint2*)&Xs[0][xci + u * 16][xp0] =
            make_uint2(*(uint32_t*)&h0, *(uint32_t*)&h1);
    }
#pragma unroll
    for (int u = 0; u < 4; u++) {
        __nv_bfloat162 g0 = __floats2bfloat162_rn(wv[u].x, wv[u].y);
        __nv_bfloat162 g1 = __floats2bfloat162_rn(wv[u].z, wv[u].w);
        *(uint2*)&Ws[0][wco + u * 32][wf] =
            make_uint2(*(uint32_t*)&g0, *(uint32_t*)&g1);
    }
    __syncthreads();

    float dacc[8][4];
#pragma unroll
    for (int nt = 0; nt < 8; nt++)
#pragma unroll
        for (int c = 0; c < 4; c++) dacc[nt][c] = 0.f;

    for (int chunk = 0; chunk < 8; chunk++) {
        const int cur = chunk & 1;
        if (chunk < 7) {
            int kc = (chunk + 1) * 32;
#pragma unroll
            for (int u = 0; u < 2; u++) {
                xv[u] = make_float4(0.f, 0.f, 0.f, 0.f);
                if (i0 + xp0 < PP)
                    xv[u] = *(const float4*)(x + (size_t)(kc + xci + u * 16) * PP + i0 + xp0);
            }
#pragma unroll
            for (int u = 0; u < 4; u++)
                wv[u] = *(const float4*)(cw + (size_t)(wco + u * 32) * CIN + kc + wf);
        }
#pragma unroll
        for (int ks = 0; ks < 2; ks++) {
            uint32_t a0, a1, a2, a3;
            {
                uint32_t addr = s2u(&Xs[cur][ks * 16 + (lq >> 1) * 8 + lr]
                                          [mb + (lq & 1) * 8]);
                LDSM4T(a0, a1, a2, a3, addr);
            }
#pragma unroll
            for (int q = 0; q < 4; q++) {
                uint32_t b0, b1, b2, b3;
                uint32_t addr = s2u(&Ws[cur][nb + (q * 2 + (lq >> 1)) * 8 + lr]
                                          [ks * 16 + (lq & 1) * 8]);
                LDSM4(b0, b1, b2, b3, addr);
                MMA16816(dacc[q*2][0], dacc[q*2][1], dacc[q*2][2], dacc[q*2][3],
                         a0, a1, a2, a3, b0, b1);
                MMA16816(dacc[q*2+1][0], dacc[q*2+1][1], dacc[q*2+1][2], dacc[q*2+1][3],
                         a0, a1, a2, a3, b2, b3);
            }
        }
        if (chunk < 7) {
            const int nxt = cur ^ 1;
#pragma unroll
            for (int u = 0; u < 2; u++) {
                __nv_bfloat162 h0 = __floats2bfloat162_rn(fmaxf(xv[u].x, 0.f), fmaxf(xv[u].y, 0.f));
                __nv_bfloat162 h1 = __floats2bfloat162_rn(fmaxf(xv[u].z, 0.f), fmaxf(xv[u].w, 0.f));
                *(uint2*)&Xs[nxt][xci + u * 16][xp0] =
                    make_uint2(*(uint32_t*)&h0, *(uint32_t*)&h1);
            }
#pragma unroll
            for (int u = 0; u < 4; u++) {
                __nv_bfloat162 g0 = __floats2bfloat162_rn(wv[u].x, wv[u].y);
                __nv_bfloat162 g1 = __floats2bfloat162_rn(wv[u].z, wv[u].w);
                *(uint2*)&Ws[nxt][wco + u * 32][wf] =
                    make_uint2(*(uint32_t*)&g0, *(uint32_t*)&g1);
            }
        }
        __syncthreads();
    }

    // epilogue: bias, BN sums (fp32), store bf16
    __nv_bfloat16* hid = g_hidbf + (size_t)s * (BB * (size_t)PP * CMID)
                                 + (size_t)b * PP * CMID;
    float lsum[16], lsq[16];
#pragma unroll
    for (int i = 0; i < 16; i++) { lsum[i] = 0.f; lsq[i] = 0.f; }

#pragma unroll
    for (int hi = 0; hi < 2; hi++) {
        int lrow = mb + hi * 8 + g;
        int row = i0 + lrow;
        if (row < PP) {
#pragma unroll
            for (int nt = 0; nt < 8; nt++) {
                int col = nb + nt * 8 + tg * 2;
                float y0 = dacc[nt][hi * 2]     + cb[col];
                float y1 = dacc[nt][hi * 2 + 1] + cb[col + 1];
                lsum[nt*2]   += y0;  lsq[nt*2]   += y0 * y0;
                lsum[nt*2+1] += y1;  lsq[nt*2+1] += y1 * y1;
                __nv_bfloat162 h = __floats2bfloat162_rn(y0, y1);
                *(uint32_t*)(hid + (size_t)row * CMID + col) = *(uint32_t*)&h;
            }
        }
    }
#pragma unroll
    for (int i = 0; i < 16; i++) {
        lsum[i] += __shfl_xor_sync(0xffffffffu, lsum[i], 4);
        lsum[i] += __shfl_xor_sync(0xffffffffu, lsum[i], 8);
        lsum[i] += __shfl_xor_sync(0xffffffffu, lsum[i], 16);
        lsq[i]  += __shfl_xor_sync(0xffffffffu, lsq[i],  4);
        lsq[i]  += __shfl_xor_sync(0xffffffffu, lsq[i],  8);
        lsq[i]  += __shfl_xor_sync(0xffffffffu, lsq[i],  16);
    }
    if (g == 0) {
#pragma unroll
        for (int nt = 0; nt < 8; nt++) {
            int col = nb + nt * 8 + tg * 2;
            atomicAdd(&ssum[col],     lsum[nt*2]);
            atomicAdd(&ssum[col + 1], lsum[nt*2+1]);
            atomicAdd(&ssq[col],      lsq[nt*2]);
            atomicAdd(&ssq[col + 1],  lsq[nt*2+1]);
        }
    }
    __syncthreads();
    if (t < 128) {
        atomicAdd(&g_sum  [s * 128 + t], ssum[t]);
        atomicAdd(&g_sumsq[s * 128 + t], ssq[t]);
    }
}

// ---------------------------------------------------------------------
__global__ void stats_kernel(const float* __restrict__ gamma,
                             const float* __restrict__ beta)
{
    int s = blockIdx.x, c = threadIdx.x;
    if (c < 128) {
        float n = (float)NPOS;
        float mean = g_sum[s * 128 + c] / n;
        float var  = g_sumsq[s * 128 + c] / n - mean * mean;
        float rs   = rsqrtf(var + 1e-5f);
        float scl  = gamma[c] * rs;
        g_scale[s * 128 + c] = scl;
        g_shift[s * 128 + c] = beta[c] - mean * scl;
    }
}

// ---------------------------------------------------------------------
// Kernel C (tensor, 64-row tiles): feat = normalize(lin_w.relu(affine(hid))+lb)
__global__ void __launch_bounds__(256) feat_kernel(
    const float* __restrict__ lw, const float* __restrict__ lb)
{
    extern __shared__ __align__(16) unsigned char smraw[];
    __nv_bfloat16* As = (__nv_bfloat16*)smraw;           // 64 x 136
    __nv_bfloat16* Ws = As + 64 * 136;                   // 128 x 136
    float* psum = (float*)(Ws + 128 * 136);              // 64

    const int s = blockIdx.z, b = blockIdx.y;
    const int i0 = blockIdx.x * 64;
    const int t = threadIdx.x;
    const int wid = t >> 5, lane = t & 31;
    const int wm = wid & 3, wn = wid >> 2;
    const int mb = wm * 16, nb = wn * 64;
    const int g = lane >> 2, tg = lane & 3;
    const int lr = lane & 7, lq = lane >> 3;

    const __nv_bfloat16* hid = g_hidbf + (size_t)s * (BB * (size_t)PP * CMID)
                                       + (size_t)b * PP * CMID;
    const float* sc = g_scale + s * 128;
    const float* sh = g_shift + s * 128;

    if (t < 64) psum[t] = 0.f;

    // stage As[row][k] (64 rows x 16 segs): affine+relu in fp32, bf16 out
#pragma unroll
    for (int u = 0; u < 4; u++) {
        int idx = u * 256 + t;
        int row = idx >> 4, seg = idx & 15;
        int k0 = seg * 8;
        uint2 out[2];
        if (i0 + row < PP) {
            uint4 v = *(const uint4*)(hid + (size_t)(i0 + row) * CMID + k0);
            uint32_t w[4] = {v.x, v.y, v.z, v.w};
#pragma unroll
            for (int j = 0; j < 4; j++) {
                float2 f = __bfloat1622float2(*(__nv_bfloat162*)&w[j]);
                float y0 = fmaxf(fmaf(f.x, sc[k0 + 2*j],     sh[k0 + 2*j]),     0.f);
                float y1 = fmaxf(fmaf(f.y, sc[k0 + 2*j + 1], sh[k0 + 2*j + 1]), 0.f);
                __nv_bfloat162 h = __floats2bfloat162_rn(y0, y1);
                ((uint32_t*)out)[j] = *(uint32_t*)&h;
            }
        } else {
            out[0] = make_uint2(0u, 0u); out[1] = make_uint2(0u, 0u);
        }
        *(uint4*)&As[row * 136 + k0] = *(uint4*)out;
    }
#pragma unroll
    for (int u = 0; u < 16; u++) {
        int idx = u * 256 + t;
        int co = idx >> 5, f = (idx & 31) * 4;
        float4 v = *(const float4*)(lw + (size_t)co * CMID + f);
        __nv_bfloat162 h0 = __floats2bfloat162_rn(v.x, v.y);
        __nv_bfloat162 h1 = __floats2bfloat162_rn(v.z, v.w);
        uint2 pk = make_uint2(*(uint32_t*)&h0, *(uint32_t*)&h1);
        *(uint2*)&Ws[co * 136 + f] = pk;
    }
    __syncthreads();

    float dacc[8][4];
#pragma unroll
    for (int nt = 0; nt < 8; nt++)
#pragma unroll
        for (int c = 0; c < 4; c++) dacc[nt][c] = 0.f;

#pragma unroll
    for (int ks = 0; ks < 8; ks++) {
        uint32_t a0, a1, a2, a3;
        {
            uint32_t addr = s2u(&As[(mb + (lq & 1) * 8 + lr) * 136
                                    + ks * 16 + (lq >> 1) * 8]);
            LDSM4(a0, a1, a2, a3, addr);
        }
#pragma unroll
        for (int q = 0; q < 4; q++) {
            uint32_t b0, b1, b2, b3;
            uint32_t addr = s2u(&Ws[(nb + (q * 2 + (lq >> 1)) * 8 + lr) * 136
                                    + ks * 16 + (lq & 1) * 8]);
            LDSM4(b0, b1, b2, b3, addr);
            MMA16816(dacc[q*2][0], dacc[q*2][1], dacc[q*2][2], dacc[q*2][3],
                     a0, a1, a2, a3, b0, b1);
            MMA16816(dacc[q*2+1][0], dacc[q*2+1][1], dacc[q*2+1][2], dacc[q*2+1][3],
                     a0, a1, a2, a3, b2, b3);
        }
    }

    // epilogue: +bias, row sumsq -> normalize -> bf16 store
    float rsq[2] = {0.f, 0.f};
#pragma unroll
    for (int hi = 0; hi < 2; hi++) {
#pragma unroll
        for (int nt = 0; nt < 8; nt++) {
            int col = nb + nt * 8 + tg * 2;
            float y0 = dacc[nt][hi*2]   + lb[col];
            float y1 = dacc[nt][hi*2+1] + lb[col + 1];
            dacc[nt][hi*2]   = y0;
            dacc[nt][hi*2+1] = y1;
            rsq[hi] = fmaf(y0, y0, fmaf(y1, y1, rsq[hi]));
        }
    }
#pragma unroll
    for (int r = 0; r < 2; r++) {
        rsq[r] += __shfl_xor_sync(0xffffffffu, rsq[r], 1);
        rsq[r] += __shfl_xor_sync(0xffffffffu, rsq[r], 2);
    }
    if (tg == 0) {
#pragma unroll
        for (int r = 0; r < 2; r++)
            atomicAdd(&psum[mb + r * 8 + g], rsq[r]);
    }
    __syncthreads();

    __nv_bfloat16* ft = g_featbf + (size_t)s * (BB * (size_t)PP * CMID)
                                 + (size_t)b * PP * CMID;
#pragma unroll
    for (int hi = 0; hi < 2; hi++) {
        int lrow = mb + hi * 8 + g;
        int row = i0 + lrow;
        if (row < PP) {
            float inv = 1.f / fmaxf(sqrtf(psum[lrow]), 1e-12f);
#pragma unroll
            for (int nt = 0; nt < 8; nt++) {
                int col = nb + nt * 8 + tg * 2;
                __nv_bfloat162 h = __floats2bfloat162_rn(
                    dacc[nt][hi*2] * inv, dacc[nt][hi*2+1] * inv);
                *(uint32_t*)(ft + (size_t)row * CMID + col) = *(uint32_t*)&h;
            }
        }
    }
}

// ---------------------------------------------------------------------
// Kernel D: bf16 mma.sync logits GEMM + fused exp-sum + diag + loss.
// (identical to R13: occupancy 2, fast/slow epilogue split, MUFU ex2)
__global__ void __launch_bounds__(256, 2) loss_kernel()
{
    extern __shared__ __align__(16) unsigned char smraw[];
    __nv_bfloat16* obuf = (__nv_bfloat16*)smraw;         // 128 x 136
    __nv_bfloat16* tbuf = obuf + 128 * 136;              // 64 x 136
    float* rowsum = (float*)(tbuf + 64 * 136);           // 128
    float* rowpos = rowsum + 128;                        // 128
    __shared__ float cred[256];

    const int b  = blockIdx.y;
    const int i0 = blockIdx.x * 128;
    const int t  = threadIdx.x;
    const int wid = t >> 5, lane = t & 31;
    const int wm = wid & 3, wn = wid >> 2;
    const int mb = wm * 32, nb = wn * 32;
    const int g = lane >> 2, tg = lane & 3;
    const int lr = lane & 7, lq = lane >> 3;
    const float invT = 1.0f / 0.07f;
    const float C2 = invT * 1.44269504088896f;   // invT * log2(e)

    const __nv_bfloat16* fo  = g_featbf + (size_t)b * PP * CMID;
    const __nv_bfloat16* ftg = g_featbf + (size_t)BB * PP * CMID + (size_t)b * PP * CMID;

    if (t < 128) rowsum[t] = 0.f;

#pragma unroll
    for (int u = 0; u < 8; u++) {
        int idx = u * 256 + t;
        int row = idx >> 4, seg = idx & 15;
        uint4 v = make_uint4(0u, 0u, 0u, 0u);
        int ig = i0 + row;
        if (ig < PP) v = *(const uint4*)(fo + (size_t)ig * CMID + seg * 8);
        *(uint4*)&obuf[row * 136 + seg * 8] = v;
    }
    __syncthreads();

    uint32_t a[2][8][4];
#pragma unroll
    for (int mt = 0; mt < 2; mt++)
#pragma unroll
        for (int ks = 0; ks < 8; ks++) {
            int mrow = mb + mt * 16 + (lq & 1) * 8 + lr;
            int koff = ks * 16 + (lq >> 1) * 8;
            uint32_t addr = s2u(&obuf[mrow * 136 + koff]);
            LDSM4(a[mt][ks][0], a[mt][ks][1], a[mt][ks][2], a[mt][ks][3], addr);
        }

    float dacc[2][4][4];
#pragma unroll
    for (int mt = 0; mt < 2; mt++)
#pragma unroll
        for (int nt = 0; nt < 4; nt++)
#pragma unroll
            for (int c = 0; c < 4; c++) dacc[mt][nt][c] = 0.f;
    float sacc[4] = {0.f, 0.f, 0.f, 0.f};

    for (int jt = 0; jt < JT; jt++) {
        int j0 = jt * 64;
        __syncthreads();
#pragma unroll
        for (int u = 0; u < 4; u++) {
            int idx = u * 256 + t;
            int row = idx >> 4, seg = idx & 15;
            uint4 v = make_uint4(0u, 0u, 0u, 0u);
            int jg = j0 + row;
            if (jg < PP) v = *(const uint4*)(ftg + (size_t)jg * CMID + seg * 8);
            *(uint4*)&tbuf[row * 136 + seg * 8] = v;
        }
        __syncthreads();

#pragma unroll
        for (int ks = 0; ks < 8; ks++) {
#pragma unroll
            for (int q = 0; q < 2; q++) {
                uint32_t b0, b1, b2, b3;
                int brow = nb + (q * 2 + (lq >> 1)) * 8 + lr;
                int koff = ks * 16 + (lq & 1) * 8;
                uint32_t addr = s2u(&tbuf[brow * 136 + koff]);
                LDSM4(b0, b1, b2, b3, addr);
#pragma unroll
                for (int mt = 0; mt < 2; mt++) {
                    MMA16816(dacc[mt][q*2][0], dacc[mt][q*2][1],
                             dacc[mt][q*2][2], dacc[mt][q*2][3],
                             a[mt][ks][0], a[mt][ks][1], a[mt][ks][2], a[mt][ks][3],
                             b0, b1);
                    MMA16816(dacc[mt][q*2+1][0], dacc[mt][q*2+1][1],
                             dacc[mt][q*2+1][2], dacc[mt][q*2+1][3],
                             a[mt][ks][0], a[mt][ks][1], a[mt][ks][2], a[mt][ks][3],
                             b2, b3);
                }
            }
        }

        int dj = jt - (blockIdx.x << 1);
        if (jt < 56 && (unsigned)dj > 1u) {
#pragma unroll
            for (int mt = 0; mt < 2; mt++)
#pragma unroll
                for (int nt = 0; nt < 4; nt++)
#pragma unroll
                    for (int c = 0; c < 4; c++) {
                        sacc[mt * 2 + (c >> 1)] += ex2(dacc[mt][nt][c] * C2);
                        dacc[mt][nt][c] = 0.f;
                    }
        } else {
#pragma unroll
            for (int mt = 0; mt < 2; mt++)
#pragma unroll
                for (int nt = 0; nt < 4; nt++)
#pragma unroll
                    for (int c = 0; c < 4; c++) {
                        float d = dacc[mt][nt][c];
                        int hi  = c >> 1;
                        int col = j0 + nb + nt * 8 + tg * 2 + (c & 1);
                        int lrow = mb + mt * 16 + hi * 8 + g;
                        if (col < PP) {
                            sacc[mt * 2 + hi] += ex2(d * C2);
                            if (col == i0 + lrow) rowpos[lrow] = d * invT;
                        }
                        dacc[mt][nt][c] = 0.f;
                    }
        }
    }

#pragma unroll
    for (int r = 0; r < 4; r++) {
        sacc[r] += __shfl_xor_sync(0xffffffffu, sacc[r], 1);
        sacc[r] += __shfl_xor_sync(0xffffffffu, sacc[r], 2);
    }
    if (tg == 0) {
#pragma unroll
        for (int r = 0; r < 4; r++) {
            int lrow = mb + (r >> 1) * 16 + (r & 1) * 8 + g;
            atomicAdd(&rowsum[lrow], sacc[r]);
        }
    }
    __syncthreads();

    float contrib = 0.f;
    if (t < 128) {
        int ig = i0 + t;
        if (ig < PP) contrib = logf(rowsum[t]) - rowpos[t];
    }
    cred[t] = contrib;
    __syncthreads();
#pragma unroll
    for (int off = 128; off > 0; off >>= 1) {
        if (t < off) cred[t] += cred[t + off];
        __syncthreads();
    }
    if (t == 0) atomicAdd(&g_loss, cred[0]);
}

// ---------------------------------------------------------------------
__global__ void finalize_kernel(float* __restrict__ out) {
    out[0] = g_loss * (1.0f / (float)NPOS);
}

// ---------------------------------------------------------------------
extern "C" void kernel_launch(void* const* d_in, const int* in_sizes, int n_in,
                              void* d_out, int out_size)
{
    const float* x0    = (const float*)d_in[0];
    const float* x1    = (const float*)d_in[1];
    const float* cw    = (const float*)d_in[2];
    const float* cb    = (const float*)d_in[3];
    const float* gamma = (const float*)d_in[4];
    const float* beta  = (const float*)d_in[5];
    const float* lw    = (const float*)d_in[6];
    const float* lb    = (const float*)d_in[7];
    float* out = (float*)d_out;

    size_t fsm = (size_t)((64 + 128) * 136) * sizeof(__nv_bfloat16)
               + 64 * sizeof(float);    // 52480 B
    cudaFuncSetAttribute((const void*)feat_kernel,
                         cudaFuncAttributeMaxDynamicSharedMemorySize, (int)fsm);
    size_t lsm = (size_t)(128 * 136 + 64 * 136) * sizeof(__nv_bfloat16)
               + 256 * sizeof(float);   // 53248 B
    cudaFuncSetAttribute((const void*)loss_kernel,
                         cudaFuncAttributeMaxDynamicSharedMemorySize, (int)lsm);

    zero_kernel<<<1, 256>>>();
    conv_kernel<<<dim3(FT, 8, 2), 256>>>(x0, x1, cw, cb);
    stats_kernel<<<2, 128>>>(gamma, beta);
    feat_kernel<<<dim3(FT, 8, 2), 256, fsm>>>(lw, lb);
    loss_kernel<<<dim3(IT, 8), 256, lsm>>>();
    finalize_kernel<<<1, 1>>>(out);
}

// round 16
// speedup vs baseline: 1.0983x; 1.0494x over previous
#include <cuda_runtime.h>
#include <cuda_bf16.h>
#include <cstdint>
#include <math.h>

#define BB    8
#define CIN   256
#define CMID  128
#define PP    3600            // 60*60 positions per batch image
#define NPOS  (BB * PP)       // 28800
#define JT    57              // ceil(3600/64) j-tiles (loss)
#define IT    29              // ceil(3600/128) i-tiles

// -------- device scratch (module-scope; no runtime alloc) --------
__device__ __nv_bfloat16 g_hidbf[(size_t)2 * BB * PP * CMID];  // conv output (bf16)
__device__ __nv_bfloat16 g_featbf[(size_t)2 * BB * PP * CMID]; // normalized features (bf16)
__device__ __nv_bfloat16 g_cwbf[CMID * CIN];                   // conv_w in bf16
__device__ __nv_bfloat16 g_lwbf[CMID * CMID];                  // lin_w in bf16
__device__ float g_sum[256], g_sumsq[256];
__device__ float g_scale[256], g_shift[256];
__device__ float g_loss;

__device__ __forceinline__ uint32_t s2u(const void* p) {
    return (uint32_t)__cvta_generic_to_shared(p);
}
__device__ __forceinline__ float ex2(float x) {      // EX2 (MUFU), base-2 exp
    float y;
    asm("ex2.approx.f32 %0, %1;" : "=f"(y) : "f"(x));
    return y;
}
#define LDSM4(r0,r1,r2,r3,addr) \
    asm volatile("ldmatrix.sync.aligned.m8n8.x4.shared.b16 {%0,%1,%2,%3}, [%4];" \
        : "=r"(r0),"=r"(r1),"=r"(r2),"=r"(r3) : "r"(addr))
#define LDSM4T(r0,r1,r2,r3,addr) \
    asm volatile("ldmatrix.sync.aligned.m8n8.x4.trans.shared.b16 {%0,%1,%2,%3}, [%4];" \
        : "=r"(r0),"=r"(r1),"=r"(r2),"=r"(r3) : "r"(addr))
#define MMA16816(d0,d1,d2,d3,a0,a1,a2,a3,b0,b1) \
    asm volatile("mma.sync.aligned.m16n8k16.row.col.f32.bf16.bf16.f32 " \
        "{%0,%1,%2,%3}, {%4,%5,%6,%7}, {%8,%9}, {%0,%1,%2,%3};" \
        : "+f"(d0),"+f"(d1),"+f"(d2),"+f"(d3) \
        : "r"(a0),"r"(a1),"r"(a2),"r"(a3),"r"(b0),"r"(b1))

// ---------------------------------------------------------------------
// Prologue: convert weights to bf16 once + zero reductions.
// 48 blocks x 256 thr; each thread handles one float4 (12288 total).
__global__ void wconv_kernel(const float* __restrict__ cw,
                             const float* __restrict__ lw)
{
    int idx = blockIdx.x * 256 + threadIdx.x;   // 0..12287
    if (blockIdx.x == 0) {
        int t = threadIdx.x;
        g_sum[t] = 0.f; g_sumsq[t] = 0.f;
        if (t == 0) g_loss = 0.f;
    }
    const float* src;
    __nv_bfloat16* dst;
    int off;
    if (idx < 8192) {                           // conv_w: 32768 floats
        src = cw;  dst = g_cwbf;  off = idx * 4;
    } else {                                    // lin_w: 16384 floats
        src = lw;  dst = g_lwbf;  off = (idx - 8192) * 4;
    }
    float4 v = *(const float4*)(src + off);
    __nv_bfloat162 h0 = __floats2bfloat162_rn(v.x, v.y);
    __nv_bfloat162 h1 = __floats2bfloat162_rn(v.z, v.w);
    *(uint2*)(dst + off) = make_uint2(*(uint32_t*)&h0, *(uint32_t*)&h1);
}

// ---------------------------------------------------------------------
// Kernel A (tensor, double-buffered, 128-pos tiles): hid = cw.relu(x) + cb
__global__ void __launch_bounds__(256) conv_kernel(
    const float* __restrict__ x0, const float* __restrict__ x1,
    const float* __restrict__ cb)
{
    const int s = blockIdx.z, b = blockIdx.y;
    const int i0 = blockIdx.x * 128;
    const float* x = (s == 0 ? x0 : x1) + (size_t)b * CIN * PP;

    __shared__ __nv_bfloat16 Xs[2][32][136];
    __shared__ __nv_bfloat16 Ws[2][128][40];
    __shared__ float ssum[128], ssq[128];

    const int t = threadIdx.x;
    const int wid = t >> 5, lane = t & 31;
    const int wm = wid & 3, wn = wid >> 2;
    const int mb = wm * 32, nb = wn * 64;
    const int g = lane >> 2, tg = lane & 3;
    const int lr = lane & 7, lq = lane >> 3;

    if (t < 128) { ssum[t] = 0.f; ssq[t] = 0.f; }

    const int xci = t >> 5, xpg = t & 31;        // x stage: +8*u on ci

    float4 xv[4];
    uint4 wv[2];
#pragma unroll
    for (int u = 0; u < 4; u++) {
        int p = i0 + xpg * 4;
        xv[u] = make_float4(0.f, 0.f, 0.f, 0.f);
        if (p < PP) xv[u] = *(const float4*)(x + (size_t)(xci + u * 8) * PP + p);
    }
#pragma unroll
    for (int u = 0; u < 2; u++) {                // Ws stage: 512 uint4/chunk
        int idx = u * 256 + t;
        int co = idx >> 2, sg = idx & 3;
        wv[u] = *(const uint4*)(g_cwbf + (size_t)co * CIN + sg * 8);
    }
#pragma unroll
    for (int u = 0; u < 4; u++) {
        __nv_bfloat162 h0 = __floats2bfloat162_rn(fmaxf(xv[u].x, 0.f), fmaxf(xv[u].y, 0.f));
        __nv_bfloat162 h1 = __floats2bfloat162_rn(fmaxf(xv[u].z, 0.f), fmaxf(xv[u].w, 0.f));
        *(uint2*)&Xs[0][xci + u * 8][xpg * 4] =
            make_uint2(*(uint32_t*)&h0, *(uint32_t*)&h1);
    }
#pragma unroll
    for (int u = 0; u < 2; u++) {
        int idx = u * 256 + t;
        int co = idx >> 2, sg = idx & 3;
        *(uint4*)&Ws[0][co][sg * 8] = wv[u];
    }
    __syncthreads();

    float dacc[2][8][4];
#pragma unroll
    for (int mt = 0; mt < 2; mt++)
#pragma unroll
        for (int nt = 0; nt < 8; nt++)
#pragma unroll
            for (int c = 0; c < 4; c++) dacc[mt][nt][c] = 0.f;

    for (int chunk = 0; chunk < 8; chunk++) {
        const int cur = chunk & 1;
        if (chunk < 7) {
            int kc = (chunk + 1) * 32;
#pragma unroll
            for (int u = 0; u < 4; u++) {
                int p = i0 + xpg * 4;
                xv[u] = make_float4(0.f, 0.f, 0.f, 0.f);
                if (p < PP)
                    xv[u] = *(const float4*)(x + (size_t)(kc + xci + u * 8) * PP + p);
            }
#pragma unroll
            for (int u = 0; u < 2; u++) {
                int idx = u * 256 + t;
                int co = idx >> 2, sg = idx & 3;
                wv[u] = *(const uint4*)(g_cwbf + (size_t)co * CIN + kc + sg * 8);
            }
        }
#pragma unroll
        for (int ks = 0; ks < 2; ks++) {
            uint32_t a[2][4];
#pragma unroll
            for (int mt = 0; mt < 2; mt++) {
                uint32_t addr = s2u(&Xs[cur][ks * 16 + (lq >> 1) * 8 + lr]
                                          [mb + mt * 16 + (lq & 1) * 8]);
                LDSM4T(a[mt][0], a[mt][1], a[mt][2], a[mt][3], addr);
            }
#pragma unroll
            for (int q = 0; q < 4; q++) {
                uint32_t b0, b1, b2, b3;
                uint32_t addr = s2u(&Ws[cur][nb + (q * 2 + (lq >> 1)) * 8 + lr]
                                          [ks * 16 + (lq & 1) * 8]);
                LDSM4(b0, b1, b2, b3, addr);
#pragma unroll
                for (int mt = 0; mt < 2; mt++) {
                    MMA16816(dacc[mt][q*2][0], dacc[mt][q*2][1],
                             dacc[mt][q*2][2], dacc[mt][q*2][3],
                             a[mt][0], a[mt][1], a[mt][2], a[mt][3], b0, b1);
                    MMA16816(dacc[mt][q*2+1][0], dacc[mt][q*2+1][1],
                             dacc[mt][q*2+1][2], dacc[mt][q*2+1][3],
                             a[mt][0], a[mt][1], a[mt][2], a[mt][3], b2, b3);
                }
            }
        }
        if (chunk < 7) {
            const int nxt = cur ^ 1;
#pragma unroll
            for (int u = 0; u < 4; u++) {
                __nv_bfloat162 h0 = __floats2bfloat162_rn(fmaxf(xv[u].x, 0.f), fmaxf(xv[u].y, 0.f));
                __nv_bfloat162 h1 = __floats2bfloat162_rn(fmaxf(xv[u].z, 0.f), fmaxf(xv[u].w, 0.f));
                *(uint2*)&Xs[nxt][xci + u * 8][xpg * 4] =
                    make_uint2(*(uint32_t*)&h0, *(uint32_t*)&h1);
            }
#pragma unroll
            for (int u = 0; u < 2; u++) {
                int idx = u * 256 + t;
                int co = idx >> 2, sg = idx & 3;
                *(uint4*)&Ws[nxt][co][sg * 8] = wv[u];
            }
        }
        __syncthreads();
    }

    __nv_bfloat16* hid = g_hidbf + (size_t)s * (BB * (size_t)PP * CMID)
                                 + (size_t)b * PP * CMID;
    float lsum[16], lsq[16];
#pragma unroll
    for (int i = 0; i < 16; i++) { lsum[i] = 0.f; lsq[i] = 0.f; }

#pragma unroll
    for (int mt = 0; mt < 2; mt++)
#pragma unroll
        for (int hi = 0; hi < 2; hi++) {
            int lrow = mb + mt * 16 + hi * 8 + g;
            int row = i0 + lrow;
            if (row < PP) {
#pragma unroll
                for (int nt = 0; nt < 8; nt++) {
                    int col = nb + nt * 8 + tg * 2;
                    float y0 = dacc[mt][nt][hi * 2]     + cb[col];
                    float y1 = dacc[mt][nt][hi * 2 + 1] + cb[col + 1];
                    lsum[nt*2]   += y0;  lsq[nt*2]   += y0 * y0;
                    lsum[nt*2+1] += y1;  lsq[nt*2+1] += y1 * y1;
                    __nv_bfloat162 h = __floats2bfloat162_rn(y0, y1);
                    *(uint32_t*)(hid + (size_t)row * CMID + col) = *(uint32_t*)&h;
                }
            }
        }
#pragma unroll
    for (int i = 0; i < 16; i++) {
        lsum[i] += __shfl_xor_sync(0xffffffffu, lsum[i], 4);
        lsum[i] += __shfl_xor_sync(0xffffffffu, lsum[i], 8);
        lsum[i] += __shfl_xor_sync(0xffffffffu, lsum[i], 16);
        lsq[i]  += __shfl_xor_sync(0xffffffffu, lsq[i],  4);
        lsq[i]  += __shfl_xor_sync(0xffffffffu, lsq[i],  8);
        lsq[i]  += __shfl_xor_sync(0xffffffffu, lsq[i],  16);
    }
    if (g == 0) {
#pragma unroll
        for (int nt = 0; nt < 8; nt++) {
            int col = nb + nt * 8 + tg * 2;
            atomicAdd(&ssum[col],     lsum[nt*2]);
            atomicAdd(&ssum[col + 1], lsum[nt*2+1]);
            atomicAdd(&ssq[col],      lsq[nt*2]);
            atomicAdd(&ssq[col + 1],  lsq[nt*2+1]);
        }
    }
    __syncthreads();
    if (t < 128) {
        atomicAdd(&g_sum  [s * 128 + t], ssum[t]);
        atomicAdd(&g_sumsq[s * 128 + t], ssq[t]);
    }
}

// ---------------------------------------------------------------------
__global__ void stats_kernel(const float* __restrict__ gamma,
                             const float* __restrict__ beta)
{
    int s = blockIdx.x, c = threadIdx.x;
    if (c < 128) {
        float n = (float)NPOS;
        float mean = g_sum[s * 128 + c] / n;
        float var  = g_sumsq[s * 128 + c] / n - mean * mean;
        float rs   = rsqrtf(var + 1e-5f);
        float scl  = gamma[c] * rs;
        g_scale[s * 128 + c] = scl;
        g_shift[s * 128 + c] = beta[c] - mean * scl;
    }
}

// ---------------------------------------------------------------------
// Kernel C (tensor, 128-row tiles): feat = normalize(lin_w.relu(affine(hid))+lb)
__global__ void __launch_bounds__(256) feat_kernel(const float* __restrict__ lb)
{
    extern __shared__ __align__(16) unsigned char smraw[];
    __nv_bfloat16* As = (__nv_bfloat16*)smraw;           // 128 x 136
    __nv_bfloat16* Ws = As + 128 * 136;                  // 128 x 136
    float* psum = (float*)(Ws + 128 * 136);              // 128

    const int s = blockIdx.z, b = blockIdx.y;
    const int i0 = blockIdx.x * 128;
    const int t = threadIdx.x;
    const int wid = t >> 5, lane = t & 31;
    const int wm = wid & 3, wn = wid >> 2;
    const int mb = wm * 32, nb = wn * 64;
    const int g = lane >> 2, tg = lane & 3;
    const int lr = lane & 7, lq = lane >> 3;

    const __nv_bfloat16* hid = g_hidbf + (size_t)s * (BB * (size_t)PP * CMID)
                                       + (size_t)b * PP * CMID;
    const float* sc = g_scale + s * 128;
    const float* sh = g_shift + s * 128;

    if (t < 128) psum[t] = 0.f;

    // stage As[p][k]: affine+relu in fp32, bf16 out
#pragma unroll
    for (int u = 0; u < 8; u++) {
        int idx = u * 256 + t;
        int row = idx >> 4, seg = idx & 15;
        int k0 = seg * 8;
        uint2 out[2];
        if (i0 + row < PP) {
            uint4 v = *(const uint4*)(hid + (size_t)(i0 + row) * CMID + k0);
            uint32_t w[4] = {v.x, v.y, v.z, v.w};
#pragma unroll
            for (int j = 0; j < 4; j++) {
                float2 f = __bfloat1622float2(*(__nv_bfloat162*)&w[j]);
                float y0 = fmaxf(fmaf(f.x, sc[k0 + 2*j],     sh[k0 + 2*j]),     0.f);
                float y1 = fmaxf(fmaf(f.y, sc[k0 + 2*j + 1], sh[k0 + 2*j + 1]), 0.f);
                __nv_bfloat162 h = __floats2bfloat162_rn(y0, y1);
                ((uint32_t*)out)[j] = *(uint32_t*)&h;
            }
        } else {
            out[0] = make_uint2(0u, 0u); out[1] = make_uint2(0u, 0u);
        }
        *(uint4*)&As[row * 136 + k0] = *(uint4*)out;
    }
    // stage Ws[co][k] from pre-converted bf16 (2048 uint4 / 256 thr = 8 it)
#pragma unroll
    for (int u = 0; u < 8; u++) {
        int idx = u * 256 + t;
        int row = idx >> 4, seg = idx & 15;
        uint4 v = *(const uint4*)(g_lwbf + (size_t)row * CMID + seg * 8);
        *(uint4*)&Ws[row * 136 + seg * 8] = v;
    }
    __syncthreads();

    float dacc[2][8][4];
#pragma unroll
    for (int mt = 0; mt < 2; mt++)
#pragma unroll
        for (int nt = 0; nt < 8; nt++)
#pragma unroll
            for (int c = 0; c < 4; c++) dacc[mt][nt][c] = 0.f;

#pragma unroll
    for (int ks = 0; ks < 8; ks++) {
        uint32_t a[2][4];
#pragma unroll
        for (int mt = 0; mt < 2; mt++) {
            uint32_t addr = s2u(&As[(mb + mt * 16 + (lq & 1) * 8 + lr) * 136
                                    + ks * 16 + (lq >> 1) * 8]);
            LDSM4(a[mt][0], a[mt][1], a[mt][2], a[mt][3], addr);
        }
#pragma unroll
        for (int q = 0; q < 4; q++) {
            uint32_t b0, b1, b2, b3;
            uint32_t addr = s2u(&Ws[(nb + (q * 2 + (lq >> 1)) * 8 + lr) * 136
                                    + ks * 16 + (lq & 1) * 8]);
            LDSM4(b0, b1, b2, b3, addr);
#pragma unroll
            for (int mt = 0; mt < 2; mt++) {
                MMA16816(dacc[mt][q*2][0], dacc[mt][q*2][1],
                         dacc[mt][q*2][2], dacc[mt][q*2][3],
                         a[mt][0], a[mt][1], a[mt][2], a[mt][3], b0, b1);
                MMA16816(dacc[mt][q*2+1][0], dacc[mt][q*2+1][1],
                         dacc[mt][q*2+1][2], dacc[mt][q*2+1][3],
                         a[mt][0], a[mt][1], a[mt][2], a[mt][3], b2, b3);
            }
        }
    }

    float rsq[4] = {0.f, 0.f, 0.f, 0.f};
#pragma unroll
    for (int mt = 0; mt < 2; mt++)
#pragma unroll
        for (int hi = 0; hi < 2; hi++) {
#pragma unroll
            for (int nt = 0; nt < 8; nt++) {
                int col = nb + nt * 8 + tg * 2;
                float y0 = dacc[mt][nt][hi*2]   + lb[col];
                float y1 = dacc[mt][nt][hi*2+1] + lb[col + 1];
                dacc[mt][nt][hi*2]   = y0;
                dacc[mt][nt][hi*2+1] = y1;
                rsq[mt*2+hi] = fmaf(y0, y0, fmaf(y1, y1, rsq[mt*2+hi]));
            }
        }
#pragma unroll
    for (int r = 0; r < 4; r++) {
        rsq[r] += __shfl_xor_sync(0xffffffffu, rsq[r], 1);
        rsq[r] += __shfl_xor_sync(0xffffffffu, rsq[r], 2);
    }
    if (tg == 0) {
#pragma unroll
        for (int r = 0; r < 4; r++) {
            int lrow = mb + (r >> 1) * 16 + (r & 1) * 8 + g;
            atomicAdd(&psum[lrow], rsq[r]);
        }
    }
    __syncthreads();

    __nv_bfloat16* ft = g_featbf + (size_t)s * (BB * (size_t)PP * CMID)
                                 + (size_t)b * PP * CMID;
#pragma unroll
    for (int mt = 0; mt < 2; mt++)
#pragma unroll
        for (int hi = 0; hi < 2; hi++) {
            int lrow = mb + mt * 16 + hi * 8 + g;
            int row = i0 + lrow;
            if (row < PP) {
                float inv = 1.f / fmaxf(sqrtf(psum[lrow]), 1e-12f);
#pragma unroll
                for (int nt = 0; nt < 8; nt++) {
                    int col = nb + nt * 8 + tg * 2;
                    __nv_bfloat162 h = __floats2bfloat162_rn(
                        dacc[mt][nt][hi*2] * inv, dacc[mt][nt][hi*2+1] * inv);
                    *(uint32_t*)(ft + (size_t)row * CMID + col) = *(uint32_t*)&h;
                }
            }
        }
}

// ---------------------------------------------------------------------
// Kernel D: bf16 mma.sync logits GEMM + fused exp-sum + diag + loss.
// (identical to R13: occupancy 2, fast/slow epilogue split, MUFU ex2)
__global__ void __launch_bounds__(256, 2) loss_kernel()
{
    extern __shared__ __align__(16) unsigned char smraw[];
    __nv_bfloat16* obuf = (__nv_bfloat16*)smraw;         // 128 x 136
    __nv_bfloat16* tbuf = obuf + 128 * 136;              // 64 x 136
    float* rowsum = (float*)(tbuf + 64 * 136);           // 128
    float* rowpos = rowsum + 128;                        // 128
    __shared__ float cred[256];

    const int b  = blockIdx.y;
    const int i0 = blockIdx.x * 128;
    const int t  = threadIdx.x;
    const int wid = t >> 5, lane = t & 31;
    const int wm = wid & 3, wn = wid >> 2;
    const int mb = wm * 32, nb = wn * 32;
    const int g = lane >> 2, tg = lane & 3;
    const int lr = lane & 7, lq = lane >> 3;
    const float invT = 1.0f / 0.07f;
    const float C2 = invT * 1.44269504088896f;   // invT * log2(e)

    const __nv_bfloat16* fo  = g_featbf + (size_t)b * PP * CMID;
    const __nv_bfloat16* ftg = g_featbf + (size_t)BB * PP * CMID + (size_t)b * PP * CMID;

    if (t < 128) rowsum[t] = 0.f;

#pragma unroll
    for (int u = 0; u < 8; u++) {
        int idx = u * 256 + t;
        int row = idx >> 4, seg = idx & 15;
        uint4 v = make_uint4(0u, 0u, 0u, 0u);
        int ig = i0 + row;
        if (ig < PP) v = *(const uint4*)(fo + (size_t)ig * CMID + seg * 8);
        *(uint4*)&obuf[row * 136 + seg * 8] = v;
    }
    __syncthreads();

    uint32_t a[2][8][4];
#pragma unroll
    for (int mt = 0; mt < 2; mt++)
#pragma unroll
        for (int ks = 0; ks < 8; ks++) {
            int mrow = mb + mt * 16 + (lq & 1) * 8 + lr;
            int koff = ks * 16 + (lq >> 1) * 8;
            uint32_t addr = s2u(&obuf[mrow * 136 + koff]);
            LDSM4(a[mt][ks][0], a[mt][ks][1], a[mt][ks][2], a[mt][ks][3], addr);
        }

    float dacc[2][4][4];
#pragma unroll
    for (int mt = 0; mt < 2; mt++)
#pragma unroll
        for (int nt = 0; nt < 4; nt++)
#pragma unroll
            for (int c = 0; c < 4; c++) dacc[mt][nt][c] = 0.f;
    float sacc[4] = {0.f, 0.f, 0.f, 0.f};

    for (int jt = 0; jt < JT; jt++) {
        int j0 = jt * 64;
        __syncthreads();
#pragma unroll
        for (int u = 0; u < 4; u++) {
            int idx = u * 256 + t;
            int row = idx >> 4, seg = idx & 15;
            uint4 v = make_uint4(0u, 0u, 0u, 0u);
            int jg = j0 + row;
            if (jg < PP) v = *(const uint4*)(ftg + (size_t)jg * CMID + seg * 8);
            *(uint4*)&tbuf[row * 136 + seg * 8] = v;
        }
        __syncthreads();

#pragma unroll
        for (int ks = 0; ks < 8; ks++) {
#pragma unroll
            for (int q = 0; q < 2; q++) {
                uint32_t b0, b1, b2, b3;
                int brow = nb + (q * 2 + (lq >> 1)) * 8 + lr;
                int koff = ks * 16 + (lq & 1) * 8;
                uint32_t addr = s2u(&tbuf[brow * 136 + koff]);
                LDSM4(b0, b1, b2, b3, addr);
#pragma unroll
                for (int mt = 0; mt < 2; mt++) {
                    MMA16816(dacc[mt][q*2][0], dacc[mt][q*2][1],
                             dacc[mt][q*2][2], dacc[mt][q*2][3],
                             a[mt][ks][0], a[mt][ks][1], a[mt][ks][2], a[mt][ks][3],
                             b0, b1);
                    MMA16816(dacc[mt][q*2+1][0], dacc[mt][q*2+1][1],
                             dacc[mt][q*2+1][2], dacc[mt][q*2+1][3],
                             a[mt][ks][0], a[mt][ks][1], a[mt][ks][2], a[mt][ks][3],
                             b2, b3);
                }
            }
        }

        int dj = jt - (blockIdx.x << 1);
        if (jt < 56 && (unsigned)dj > 1u) {
#pragma unroll
            for (int mt = 0; mt < 2; mt++)
#pragma unroll
                for (int nt = 0; nt < 4; nt++)
#pragma unroll
                    for (int c = 0; c < 4; c++) {
                        sacc[mt * 2 + (c >> 1)] += ex2(dacc[mt][nt][c] * C2);
                        dacc[mt][nt][c] = 0.f;
                    }
        } else {
#pragma unroll
            for (int mt = 0; mt < 2; mt++)
#pragma unroll
                for (int nt = 0; nt < 4; nt++)
#pragma unroll
                    for (int c = 0; c < 4; c++) {
                        float d = dacc[mt][nt][c];
                        int hi  = c >> 1;
                        int col = j0 + nb + nt * 8 + tg * 2 + (c & 1);
                        int lrow = mb + mt * 16 + hi * 8 + g;
                        if (col < PP) {
                            sacc[mt * 2 + hi] += ex2(d * C2);
                            if (col == i0 + lrow) rowpos[lrow] = d * invT;
                        }
                        dacc[mt][nt][c] = 0.f;
                    }
        }
    }

#pragma unroll
    for (int r = 0; r < 4; r++) {
        sacc[r] += __shfl_xor_sync(0xffffffffu, sacc[r], 1);
        sacc[r] += __shfl_xor_sync(0xffffffffu, sacc[r], 2);
    }
    if (tg == 0) {
#pragma unroll
        for (int r = 0; r < 4; r++) {
            int lrow = mb + (r >> 1) * 16 + (r & 1) * 8 + g;
            atomicAdd(&rowsum[lrow], sacc[r]);
        }
    }
    __syncthreads();

    float contrib = 0.f;
    if (t < 128) {
        int ig = i0 + t;
        if (ig < PP) contrib = logf(rowsum[t]) - rowpos[t];
    }
    cred[t] = contrib;
    __syncthreads();
#pragma unroll
    for (int off = 128; off > 0; off >>= 1) {
        if (t < off) cred[t] += cred[t + off];
        __syncthreads();
    }
    if (t == 0) atomicAdd(&g_loss, cred[0]);
}

// ---------------------------------------------------------------------
__global__ void finalize_kernel(float* __restrict__ out) {
    out[0] = g_loss * (1.0f / (float)NPOS);
}

// ---------------------------------------------------------------------
extern "C" void kernel_launch(void* const* d_in, const int* in_sizes, int n_in,
                              void* d_out, int out_size)
{
    const float* x0    = (const float*)d_in[0];
    const float* x1    = (const float*)d_in[1];
    const float* cw    = (const float*)d_in[2];
    const float* cb    = (const float*)d_in[3];
    const float* gamma = (const float*)d_in[4];
    const float* beta  = (const float*)d_in[5];
    const float* lw    = (const float*)d_in[6];
    const float* lb    = (const float*)d_in[7];
    float* out = (float*)d_out;

    size_t fsm = (size_t)(2 * 128 * 136) * sizeof(__nv_bfloat16)
               + 128 * sizeof(float);   // 70144 B
    cudaFuncSetAttribute((const void*)feat_kernel,
                         cudaFuncAttributeMaxDynamicSharedMemorySize, (int)fsm);
    size_t lsm = (size_t)(128 * 136 + 64 * 136) * sizeof(__nv_bfloat16)
               + 256 * sizeof(float);   // 53248 B
    cudaFuncSetAttribute((const void*)loss_kernel,
                         cudaFuncAttributeMaxDynamicSharedMemorySize, (int)lsm);

    wconv_kernel<<<48, 256>>>(cw, lw);
    conv_kernel<<<dim3(IT, 8, 2), 256>>>(x0, x1, cb);
    stats_kernel<<<2, 128>>>(gamma, beta);
    feat_kernel<<<dim3(IT, 8, 2), 256, fsm>>>(lb);
    loss_kernel<<<dim3(IT, 8), 256, lsm>>>();
    finalize_kernel<<<1, 1>>>(out);
}

// round 17
// speedup vs baseline: 1.1210x; 1.0207x over previous
#include <cuda_runtime.h>
#include <cuda_bf16.h>
#include <cstdint>
#include <math.h>

#define BB    8
#define CIN   256
#define CMID  128
#define PP    3600            // 60*60 positions per batch image
#define NPOS  (BB * PP)       // 28800
#define JT    57              // ceil(3600/64) j-tiles (loss)
#define IT    29              // ceil(3600/128) i-tiles

// -------- device scratch (module-scope; no runtime alloc) --------
__device__ __nv_bfloat16 g_hidbf[(size_t)2 * BB * PP * CMID];  // conv output (bf16)
__device__ __nv_bfloat16 g_featbf[(size_t)2 * BB * PP * CMID]; // normalized features (bf16)
__device__ __nv_bfloat16 g_cwbf[CMID * CIN];                   // conv_w in bf16
__device__ __nv_bfloat16 g_lwbf[CMID * CMID];                  // lin_w in bf16
__device__ float g_sum[256], g_sumsq[256];
__device__ float g_loss;
__device__ unsigned int g_cnt;

__device__ __forceinline__ uint32_t s2u(const void* p) {
    return (uint32_t)__cvta_generic_to_shared(p);
}
__device__ __forceinline__ float ex2(float x) {      // EX2 (MUFU), base-2 exp
    float y;
    asm("ex2.approx.f32 %0, %1;" : "=f"(y) : "f"(x));
    return y;
}
#define LDSM4(r0,r1,r2,r3,addr) \
    asm volatile("ldmatrix.sync.aligned.m8n8.x4.shared.b16 {%0,%1,%2,%3}, [%4];" \
        : "=r"(r0),"=r"(r1),"=r"(r2),"=r"(r3) : "r"(addr))
#define LDSM4T(r0,r1,r2,r3,addr) \
    asm volatile("ldmatrix.sync.aligned.m8n8.x4.trans.shared.b16 {%0,%1,%2,%3}, [%4];" \
        : "=r"(r0),"=r"(r1),"=r"(r2),"=r"(r3) : "r"(addr))
#define MMA16816(d0,d1,d2,d3,a0,a1,a2,a3,b0,b1) \
    asm volatile("mma.sync.aligned.m16n8k16.row.col.f32.bf16.bf16.f32 " \
        "{%0,%1,%2,%3}, {%4,%5,%6,%7}, {%8,%9}, {%0,%1,%2,%3};" \
        : "+f"(d0),"+f"(d1),"+f"(d2),"+f"(d3) \
        : "r"(a0),"r"(a1),"r"(a2),"r"(a3),"r"(b0),"r"(b1))

// ---------------------------------------------------------------------
// Prologue: convert weights to bf16 once + zero reductions/counters.
__global__ void wconv_kernel(const float* __restrict__ cw,
                             const float* __restrict__ lw)
{
    int idx = blockIdx.x * 256 + threadIdx.x;   // 0..12287
    if (blockIdx.x == 0) {
        int t = threadIdx.x;
        g_sum[t] = 0.f; g_sumsq[t] = 0.f;
        if (t == 0) { g_loss = 0.f; g_cnt = 0u; }
    }
    const float* src;
    __nv_bfloat16* dst;
    int off;
    if (idx < 8192) {                           // conv_w: 32768 floats
        src = cw;  dst = g_cwbf;  off = idx * 4;
    } else {                                    // lin_w: 16384 floats
        src = lw;  dst = g_lwbf;  off = (idx - 8192) * 4;
    }
    float4 v = *(const float4*)(src + off);
    __nv_bfloat162 h0 = __floats2bfloat162_rn(v.x, v.y);
    __nv_bfloat162 h1 = __floats2bfloat162_rn(v.z, v.w);
    *(uint2*)(dst + off) = make_uint2(*(uint32_t*)&h0, *(uint32_t*)&h1);
}

// ---------------------------------------------------------------------
// Kernel A (tensor, double-buffered, 128-pos tiles): hid = cw.relu(x) + cb
__global__ void __launch_bounds__(256) conv_kernel(
    const float* __restrict__ x0, const float* __restrict__ x1,
    const float* __restrict__ cb)
{
    const int s = blockIdx.z, b = blockIdx.y;
    const int i0 = blockIdx.x * 128;
    const float* x = (s == 0 ? x0 : x1) + (size_t)b * CIN * PP;

    __shared__ __nv_bfloat16 Xs[2][32][136];
    __shared__ __nv_bfloat16 Ws[2][128][40];
    __shared__ float ssum[128], ssq[128];

    const int t = threadIdx.x;
    const int wid = t >> 5, lane = t & 31;
    const int wm = wid & 3, wn = wid >> 2;
    const int mb = wm * 32, nb = wn * 64;
    const int g = lane >> 2, tg = lane & 3;
    const int lr = lane & 7, lq = lane >> 3;

    if (t < 128) { ssum[t] = 0.f; ssq[t] = 0.f; }

    const int xci = t >> 5, xpg = t & 31;        // x stage: +8*u on ci

    float4 xv[4];
    uint4 wv[2];
#pragma unroll
    for (int u = 0; u < 4; u++) {
        int p = i0 + xpg * 4;
        xv[u] = make_float4(0.f, 0.f, 0.f, 0.f);
        if (p < PP) xv[u] = *(const float4*)(x + (size_t)(xci + u * 8) * PP + p);
    }
#pragma unroll
    for (int u = 0; u < 2; u++) {
        int idx = u * 256 + t;
        int co = idx >> 2, sg = idx & 3;
        wv[u] = *(const uint4*)(g_cwbf + (size_t)co * CIN + sg * 8);
    }
#pragma unroll
    for (int u = 0; u < 4; u++) {
        __nv_bfloat162 h0 = __floats2bfloat162_rn(fmaxf(xv[u].x, 0.f), fmaxf(xv[u].y, 0.f));
        __nv_bfloat162 h1 = __floats2bfloat162_rn(fmaxf(xv[u].z, 0.f), fmaxf(xv[u].w, 0.f));
        *(uint2*)&Xs[0][xci + u * 8][xpg * 4] =
            make_uint2(*(uint32_t*)&h0, *(uint32_t*)&h1);
    }
#pragma unroll
    for (int u = 0; u < 2; u++) {
        int idx = u * 256 + t;
        int co = idx >> 2, sg = idx & 3;
        *(uint4*)&Ws[0][co][sg * 8] = wv[u];
    }
    __syncthreads();

    float dacc[2][8][4];
#pragma unroll
    for (int mt = 0; mt < 2; mt++)
#pragma unroll
        for (int nt = 0; nt < 8; nt++)
#pragma unroll
            for (int c = 0; c < 4; c++) dacc[mt][nt][c] = 0.f;

    for (int chunk = 0; chunk < 8; chunk++) {
        const int cur = chunk & 1;
        if (chunk < 7) {
            int kc = (chunk + 1) * 32;
#pragma unroll
            for (int u = 0; u < 4; u++) {
                int p = i0 + xpg * 4;
                xv[u] = make_float4(0.f, 0.f, 0.f, 0.f);
                if (p < PP)
                    xv[u] = *(const float4*)(x + (size_t)(kc + xci + u * 8) * PP + p);
            }
#pragma unroll
            for (int u = 0; u < 2; u++) {
                int idx = u * 256 + t;
                int co = idx >> 2, sg = idx & 3;
                wv[u] = *(const uint4*)(g_cwbf + (size_t)co * CIN + kc + sg * 8);
            }
        }
#pragma unroll
        for (int ks = 0; ks < 2; ks++) {
            uint32_t a[2][4];
#pragma unroll
            for (int mt = 0; mt < 2; mt++) {
                uint32_t addr = s2u(&Xs[cur][ks * 16 + (lq >> 1) * 8 + lr]
                                          [mb + mt * 16 + (lq & 1) * 8]);
                LDSM4T(a[mt][0], a[mt][1], a[mt][2], a[mt][3], addr);
            }
#pragma unroll
            for (int q = 0; q < 4; q++) {
                uint32_t b0, b1, b2, b3;
                uint32_t addr = s2u(&Ws[cur][nb + (q * 2 + (lq >> 1)) * 8 + lr]
                                          [ks * 16 + (lq & 1) * 8]);
                LDSM4(b0, b1, b2, b3, addr);
#pragma unroll
                for (int mt = 0; mt < 2; mt++) {
                    MMA16816(dacc[mt][q*2][0], dacc[mt][q*2][1],
                             dacc[mt][q*2][2], dacc[mt][q*2][3],
                             a[mt][0], a[mt][1], a[mt][2], a[mt][3], b0, b1);
                    MMA16816(dacc[mt][q*2+1][0], dacc[mt][q*2+1][1],
                             dacc[mt][q*2+1][2], dacc[mt][q*2+1][3],
                             a[mt][0], a[mt][1], a[mt][2], a[mt][3], b2, b3);
                }
            }
        }
        if (chunk < 7) {
            const int nxt = cur ^ 1;
#pragma unroll
            for (int u = 0; u < 4; u++) {
                __nv_bfloat162 h0 = __floats2bfloat162_rn(fmaxf(xv[u].x, 0.f), fmaxf(xv[u].y, 0.f));
                __nv_bfloat162 h1 = __floats2bfloat162_rn(fmaxf(xv[u].z, 0.f), fmaxf(xv[u].w, 0.f));
                *(uint2*)&Xs[nxt][xci + u * 8][xpg * 4] =
                    make_uint2(*(uint32_t*)&h0, *(uint32_t*)&h1);
            }
#pragma unroll
            for (int u = 0; u < 2; u++) {
                int idx = u * 256 + t;
                int co = idx >> 2, sg = idx & 3;
                *(uint4*)&Ws[nxt][co][sg * 8] = wv[u];
            }
        }
        __syncthreads();
    }

    __nv_bfloat16* hid = g_hidbf + (size_t)s * (BB * (size_t)PP * CMID)
                                 + (size_t)b * PP * CMID;
    float lsum[16], lsq[16];
#pragma unroll
    for (int i = 0; i < 16; i++) { lsum[i] = 0.f; lsq[i] = 0.f; }

#pragma unroll
    for (int mt = 0; mt < 2; mt++)
#pragma unroll
        for (int hi = 0; hi < 2; hi++) {
            int lrow = mb + mt * 16 + hi * 8 + g;
            int row = i0 + lrow;
            if (row < PP) {
#pragma unroll
                for (int nt = 0; nt < 8; nt++) {
                    int col = nb + nt * 8 + tg * 2;
                    float y0 = dacc[mt][nt][hi * 2]     + cb[col];
                    float y1 = dacc[mt][nt][hi * 2 + 1] + cb[col + 1];
                    lsum[nt*2]   += y0;  lsq[nt*2]   += y0 * y0;
                    lsum[nt*2+1] += y1;  lsq[nt*2+1] += y1 * y1;
                    __nv_bfloat162 h = __floats2bfloat162_rn(y0, y1);
                    *(uint32_t*)(hid + (size_t)row * CMID + col) = *(uint32_t*)&h;
                }
            }
        }
#pragma unroll
    for (int i = 0; i < 16; i++) {
        lsum[i] += __shfl_xor_sync(0xffffffffu, lsum[i], 4);
        lsum[i] += __shfl_xor_sync(0xffffffffu, lsum[i], 8);
        lsum[i] += __shfl_xor_sync(0xffffffffu, lsum[i], 16);
        lsq[i]  += __shfl_xor_sync(0xffffffffu, lsq[i],  4);
        lsq[i]  += __shfl_xor_sync(0xffffffffu, lsq[i],  8);
        lsq[i]  += __shfl_xor_sync(0xffffffffu, lsq[i],  16);
    }
    if (g == 0) {
#pragma unroll
        for (int nt = 0; nt < 8; nt++) {
            int col = nb + nt * 8 + tg * 2;
            atomicAdd(&ssum[col],     lsum[nt*2]);
            atomicAdd(&ssum[col + 1], lsum[nt*2+1]);
            atomicAdd(&ssq[col],      lsq[nt*2]);
            atomicAdd(&ssq[col + 1],  lsq[nt*2+1]);
        }
    }
    __syncthreads();
    if (t < 128) {
        atomicAdd(&g_sum  [s * 128 + t], ssum[t]);
        atomicAdd(&g_sumsq[s * 128 + t], ssq[t]);
    }
}

// ---------------------------------------------------------------------
// Kernel C (tensor, 128-row tiles): feat = normalize(lin_w.relu(affine(hid))+lb)
// BN scale/shift computed in-kernel from g_sum/g_sumsq (stats kernel fused).
__global__ void __launch_bounds__(256) feat_kernel(
    const float* __restrict__ gamma, const float* __restrict__ beta,
    const float* __restrict__ lb)
{
    extern __shared__ __align__(16) unsigned char smraw[];
    __nv_bfloat16* As = (__nv_bfloat16*)smraw;           // 128 x 136
    __nv_bfloat16* Ws = As + 128 * 136;                  // 128 x 136
    float* psum = (float*)(Ws + 128 * 136);              // 128
    float* scs  = psum + 128;                            // 128
    float* shs  = scs + 128;                             // 128

    const int s = blockIdx.z, b = blockIdx.y;
    const int i0 = blockIdx.x * 128;
    const int t = threadIdx.x;
    const int wid = t >> 5, lane = t & 31;
    const int wm = wid & 3, wn = wid >> 2;
    const int mb = wm * 32, nb = wn * 64;
    const int g = lane >> 2, tg = lane & 3;
    const int lr = lane & 7, lq = lane >> 3;

    const __nv_bfloat16* hid = g_hidbf + (size_t)s * (BB * (size_t)PP * CMID)
                                       + (size_t)b * PP * CMID;

    if (t < 128) {
        psum[t] = 0.f;
        float n = (float)NPOS;
        float mean = g_sum[s * 128 + t] / n;
        float var  = g_sumsq[s * 128 + t] / n - mean * mean;
        float rs   = rsqrtf(var + 1e-5f);
        float scl  = gamma[t] * rs;
        scs[t] = scl;
        shs[t] = beta[t] - mean * scl;
    }
    __syncthreads();

    // stage As[p][k]: affine+relu in fp32 (scales from smem), bf16 out
#pragma unroll
    for (int u = 0; u < 8; u++) {
        int idx = u * 256 + t;
        int row = idx >> 4, seg = idx & 15;
        int k0 = seg * 8;
        uint2 out[2];
        if (i0 + row < PP) {
            uint4 v = *(const uint4*)(hid + (size_t)(i0 + row) * CMID + k0);
            uint32_t w[4] = {v.x, v.y, v.z, v.w};
#pragma unroll
            for (int j = 0; j < 4; j++) {
                float2 f = __bfloat1622float2(*(__nv_bfloat162*)&w[j]);
                float y0 = fmaxf(fmaf(f.x, scs[k0 + 2*j],     shs[k0 + 2*j]),     0.f);
                float y1 = fmaxf(fmaf(f.y, scs[k0 + 2*j + 1], shs[k0 + 2*j + 1]), 0.f);
                __nv_bfloat162 h = __floats2bfloat162_rn(y0, y1);
                ((uint32_t*)out)[j] = *(uint32_t*)&h;
            }
        } else {
            out[0] = make_uint2(0u, 0u); out[1] = make_uint2(0u, 0u);
        }
        *(uint4*)&As[row * 136 + k0] = *(uint4*)out;
    }
    // stage Ws[co][k] from pre-converted bf16
#pragma unroll
    for (int u = 0; u < 8; u++) {
        int idx = u * 256 + t;
        int row = idx >> 4, seg = idx & 15;
        uint4 v = *(const uint4*)(g_lwbf + (size_t)row * CMID + seg * 8);
        *(uint4*)&Ws[row * 136 + seg * 8] = v;
    }
    __syncthreads();

    float dacc[2][8][4];
#pragma unroll
    for (int mt = 0; mt < 2; mt++)
#pragma unroll
        for (int nt = 0; nt < 8; nt++)
#pragma unroll
            for (int c = 0; c < 4; c++) dacc[mt][nt][c] = 0.f;

#pragma unroll
    for (int ks = 0; ks < 8; ks++) {
        uint32_t a[2][4];
#pragma unroll
        for (int mt = 0; mt < 2; mt++) {
            uint32_t addr = s2u(&As[(mb + mt * 16 + (lq & 1) * 8 + lr) * 136
                                    + ks * 16 + (lq >> 1) * 8]);
            LDSM4(a[mt][0], a[mt][1], a[mt][2], a[mt][3], addr);
        }
#pragma unroll
        for (int q = 0; q < 4; q++) {
            uint32_t b0, b1, b2, b3;
            uint32_t addr = s2u(&Ws[(nb + (q * 2 + (lq >> 1)) * 8 + lr) * 136
                                    + ks * 16 + (lq & 1) * 8]);
            LDSM4(b0, b1, b2, b3, addr);
#pragma unroll
            for (int mt = 0; mt < 2; mt++) {
                MMA16816(dacc[mt][q*2][0], dacc[mt][q*2][1],
                         dacc[mt][q*2][2], dacc[mt][q*2][3],
                         a[mt][0], a[mt][1], a[mt][2], a[mt][3], b0, b1);
                MMA16816(dacc[mt][q*2+1][0], dacc[mt][q*2+1][1],
                         dacc[mt][q*2+1][2], dacc[mt][q*2+1][3],
                         a[mt][0], a[mt][1], a[mt][2], a[mt][3], b2, b3);
            }
        }
    }

    float rsq[4] = {0.f, 0.f, 0.f, 0.f};
#pragma unroll
    for (int mt = 0; mt < 2; mt++)
#pragma unroll
        for (int hi = 0; hi < 2; hi++) {
#pragma unroll
            for (int nt = 0; nt < 8; nt++) {
                int col = nb + nt * 8 + tg * 2;
                float y0 = dacc[mt][nt][hi*2]   + lb[col];
                float y1 = dacc[mt][nt][hi*2+1] + lb[col + 1];
                dacc[mt][nt][hi*2]   = y0;
                dacc[mt][nt][hi*2+1] = y1;
                rsq[mt*2+hi] = fmaf(y0, y0, fmaf(y1, y1, rsq[mt*2+hi]));
            }
        }
#pragma unroll
    for (int r = 0; r < 4; r++) {
        rsq[r] += __shfl_xor_sync(0xffffffffu, rsq[r], 1);
        rsq[r] += __shfl_xor_sync(0xffffffffu, rsq[r], 2);
    }
    if (tg == 0) {
#pragma unroll
        for (int r = 0; r < 4; r++) {
            int lrow = mb + (r >> 1) * 16 + (r & 1) * 8 + g;
            atomicAdd(&psum[lrow], rsq[r]);
        }
    }
    __syncthreads();

    __nv_bfloat16* ft = g_featbf + (size_t)s * (BB * (size_t)PP * CMID)
                                 + (size_t)b * PP * CMID;
#pragma unroll
    for (int mt = 0; mt < 2; mt++)
#pragma unroll
        for (int hi = 0; hi < 2; hi++) {
            int lrow = mb + mt * 16 + hi * 8 + g;
            int row = i0 + lrow;
            if (row < PP) {
                float inv = 1.f / fmaxf(sqrtf(psum[lrow]), 1e-12f);
#pragma unroll
                for (int nt = 0; nt < 8; nt++) {
                    int col = nb + nt * 8 + tg * 2;
                    __nv_bfloat162 h = __floats2bfloat162_rn(
                        dacc[mt][nt][hi*2] * inv, dacc[mt][nt][hi*2+1] * inv);
                    *(uint32_t*)(ft + (size_t)row * CMID + col) = *(uint32_t*)&h;
                }
            }
        }
}

// ---------------------------------------------------------------------
// Kernel D: bf16 mma.sync logits GEMM + fused exp-sum + diag + loss.
// Last CTA (ticket) writes the final output (finalize kernel fused).
__global__ void __launch_bounds__(256, 2) loss_kernel(float* __restrict__ out)
{
    extern __shared__ __align__(16) unsigned char smraw[];
    __nv_bfloat16* obuf = (__nv_bfloat16*)smraw;         // 128 x 136
    __nv_bfloat16* tbuf = obuf + 128 * 136;              // 64 x 136
    float* rowsum = (float*)(tbuf + 64 * 136);           // 128
    float* rowpos = rowsum + 128;                        // 128
    __shared__ float cred[256];

    const int b  = blockIdx.y;
    const int i0 = blockIdx.x * 128;
    const int t  = threadIdx.x;
    const int wid = t >> 5, lane = t & 31;
    const int wm = wid & 3, wn = wid >> 2;
    const int mb = wm * 32, nb = wn * 32;
    const int g = lane >> 2, tg = lane & 3;
    const int lr = lane & 7, lq = lane >> 3;
    const float invT = 1.0f / 0.07f;
    const float C2 = invT * 1.44269504088896f;   // invT * log2(e)

    const __nv_bfloat16* fo  = g_featbf + (size_t)b * PP * CMID;
    const __nv_bfloat16* ftg = g_featbf + (size_t)BB * PP * CMID + (size_t)b * PP * CMID;

    if (t < 128) rowsum[t] = 0.f;

#pragma unroll
    for (int u = 0; u < 8; u++) {
        int idx = u * 256 + t;
        int row = idx >> 4, seg = idx & 15;
        uint4 v = make_uint4(0u, 0u, 0u, 0u);
        int ig = i0 + row;
        if (ig < PP) v = *(const uint4*)(fo + (size_t)ig * CMID + seg * 8);
        *(uint4*)&obuf[row * 136 + seg * 8] = v;
    }
    __syncthreads();

    uint32_t a[2][8][4];
#pragma unroll
    for (int mt = 0; mt < 2; mt++)
#pragma unroll
        for (int ks = 0; ks < 8; ks++) {
            int mrow = mb + mt * 16 + (lq & 1) * 8 + lr;
            int koff = ks * 16 + (lq >> 1) * 8;
            uint32_t addr = s2u(&obuf[mrow * 136 + koff]);
            LDSM4(a[mt][ks][0], a[mt][ks][1], a[mt][ks][2], a[mt][ks][3], addr);
        }

    float dacc[2][4][4];
#pragma unroll
    for (int mt = 0; mt < 2; mt++)
#pragma unroll
        for (int nt = 0; nt < 4; nt++)
#pragma unroll
            for (int c = 0; c < 4; c++) dacc[mt][nt][c] = 0.f;
    float sacc[4] = {0.f, 0.f, 0.f, 0.f};

    for (int jt = 0; jt < JT; jt++) {
        int j0 = jt * 64;
        __syncthreads();
#pragma unroll
        for (int u = 0; u < 4; u++) {
            int idx = u * 256 + t;
            int row = idx >> 4, seg = idx & 15;
            uint4 v = make_uint4(0u, 0u, 0u, 0u);
            int jg = j0 + row;
            if (jg < PP) v = *(const uint4*)(ftg + (size_t)jg * CMID + seg * 8);
            *(uint4*)&tbuf[row * 136 + seg * 8] = v;
        }
        __syncthreads();

#pragma unroll
        for (int ks = 0; ks < 8; ks++) {
#pragma unroll
            for (int q = 0; q < 2; q++) {
                uint32_t b0, b1, b2, b3;
                int brow = nb + (q * 2 + (lq >> 1)) * 8 + lr;
                int koff = ks * 16 + (lq & 1) * 8;
                uint32_t addr = s2u(&tbuf[brow * 136 + koff]);
                LDSM4(b0, b1, b2, b3, addr);
#pragma unroll
                for (int mt = 0; mt < 2; mt++) {
                    MMA16816(dacc[mt][q*2][0], dacc[mt][q*2][1],
                             dacc[mt][q*2][2], dacc[mt][q*2][3],
                             a[mt][ks][0], a[mt][ks][1], a[mt][ks][2], a[mt][ks][3],
                             b0, b1);
                    MMA16816(dacc[mt][q*2+1][0], dacc[mt][q*2+1][1],
                             dacc[mt][q*2+1][2], dacc[mt][q*2+1][3],
                             a[mt][ks][0], a[mt][ks][1], a[mt][ks][2], a[mt][ks][3],
                             b2, b3);
                }
            }
        }

        int dj = jt - (blockIdx.x << 1);
        if (jt < 56 && (unsigned)dj > 1u) {
#pragma unroll
            for (int mt = 0; mt < 2; mt++)
#pragma unroll
                for (int nt = 0; nt < 4; nt++)
#pragma unroll
                    for (int c = 0; c < 4; c++) {
                        sacc[mt * 2 + (c >> 1)] += ex2(dacc[mt][nt][c] * C2);
                        dacc[mt][nt][c] = 0.f;
                    }
        } else {
#pragma unroll
            for (int mt = 0; mt < 2; mt++)
#pragma unroll
                for (int nt = 0; nt < 4; nt++)
#pragma unroll
                    for (int c = 0; c < 4; c++) {
                        float d = dacc[mt][nt][c];
                        int hi  = c >> 1;
                        int col = j0 + nb + nt * 8 + tg * 2 + (c & 1);
                        int lrow = mb + mt * 16 + hi * 8 + g;
                        if (col < PP) {
                            sacc[mt * 2 + hi] += ex2(d * C2);
                            if (col == i0 + lrow) rowpos[lrow] = d * invT;
                        }
                        dacc[mt][nt][c] = 0.f;
                    }
        }
    }

#pragma unroll
    for (int r = 0; r < 4; r++) {
        sacc[r] += __shfl_xor_sync(0xffffffffu, sacc[r], 1);
        sacc[r] += __shfl_xor_sync(0xffffffffu, sacc[r], 2);
    }
    if (tg == 0) {
#pragma unroll
        for (int r = 0; r < 4; r++) {
            int lrow = mb + (r >> 1) * 16 + (r & 1) * 8 + g;
            atomicAdd(&rowsum[lrow], sacc[r]);
        }
    }
    __syncthreads();

    float contrib = 0.f;
    if (t < 128) {
        int ig = i0 + t;
        if (ig < PP) contrib = logf(rowsum[t]) - rowpos[t];
    }
    cred[t] = contrib;
    __syncthreads();
#pragma unroll
    for (int off = 128; off > 0; off >>= 1) {
        if (t < off) cred[t] += cred[t + off];
        __syncthreads();
    }
    if (t == 0) {
        atomicAdd(&g_loss, cred[0]);
        __threadfence();
        unsigned int ticket = atomicAdd(&g_cnt, 1u);
        if (ticket == (unsigned)(IT * BB) - 1u) {
            float total = atomicAdd(&g_loss, 0.f);   // L2-coherent read
            out[0] = total * (1.0f / (float)NPOS);
        }
    }
}

// ---------------------------------------------------------------------
extern "C" void kernel_launch(void* const* d_in, const int* in_sizes, int n_in,
                              void* d_out, int out_size)
{
    const float* x0    = (const float*)d_in[0];
    const float* x1    = (const float*)d_in[1];
    const float* cw    = (const float*)d_in[2];
    const float* cb    = (const float*)d_in[3];
    const float* gamma = (const float*)d_in[4];
    const float* beta  = (const float*)d_in[5];
    const float* lw    = (const float*)d_in[6];
    const float* lb    = (const float*)d_in[7];
    float* out = (float*)d_out;

    size_t fsm = (size_t)(2 * 128 * 136) * sizeof(__nv_bfloat16)
               + (128 + 256) * sizeof(float);   // 71168 B
    cudaFuncSetAttribute((const void*)feat_kernel,
                         cudaFuncAttributeMaxDynamicSharedMemorySize, (int)fsm);
    size_t lsm = (size_t)(128 * 136 + 64 * 136) * sizeof(__nv_bfloat16)
               + 256 * sizeof(float);   // 53248 B
    cudaFuncSetAttribute((const void*)loss_kernel,
                         cudaFuncAttributeMaxDynamicSharedMemorySize, (int)lsm);

    wconv_kernel<<<48, 256>>>(cw, lw);
    conv_kernel<<<dim3(IT, 8, 2), 256>>>(x0, x1, cb);
    feat_kernel<<<dim3(IT, 8, 2), 256, fsm>>>(gamma, beta, lb);
    loss_kernel<<<dim3(IT, 8), 256, lsm>>>(out);
}